// round 2
// baseline (speedup 1.0000x reference)
#include <cuda_runtime.h>

#define Nn 100000
#define Ee 1600000
#define ETOT 1700000   // Ee + Nn self loops
#define NB 98          // ceil(Nn/1024)

// ---------------- scratch (device globals; no allocation) ----------------
__device__ int   g_count[Nn];
__device__ int   g_rowptr[Nn + 1];
__device__ int   g_wptr[Nn];
__device__ int   g_bsum[NB];
__device__ int   g_boff[NB];
__device__ int   g_src[ETOT];
__device__ float g_feat[Nn * 64];   // per-layer transformed features h = x @ W
__device__ float g_buf[Nn * 64];    // per-layer aggregated output (ping-pong)
__device__ float g_alsrc[Nn * 2];   // per-node attention logits (src side)
__device__ float g_aldst[Nn * 2];   // per-node attention logits (dst side)

__device__ __forceinline__ float lrelu(float x) { return fmaxf(x, 0.2f * x); }

// ---------------- CSR construction ----------------
__global__ void k_zero() {
    int i = blockIdx.x * blockDim.x + threadIdx.x;
    if (i < Nn) g_count[i] = 0;
}

__global__ void k_hist(const int* __restrict__ ei) {
    int i = blockIdx.x * blockDim.x + threadIdx.x;
    if (i >= ETOT) return;
    int d = (i < Ee) ? ei[Ee + i] : (i - Ee);
    atomicAdd(&g_count[d], 1);
}

__global__ void k_scan1() {
    __shared__ int s[1024];
    int t = threadIdx.x, i = blockIdx.x * 1024 + t;
    int v = (i < Nn) ? g_count[i] : 0;
    s[t] = v;
    __syncthreads();
    for (int o = 1; o < 1024; o <<= 1) {
        int a = (t >= o) ? s[t - o] : 0;
        __syncthreads();
        s[t] += a;
        __syncthreads();
    }
    if (i < Nn) g_rowptr[i + 1] = s[t];
    if (t == 1023) g_bsum[blockIdx.x] = s[t];
}

__global__ void k_scan2() {
    __shared__ int s[128];
    int t = threadIdx.x;
    s[t] = (t < NB) ? g_bsum[t] : 0;
    __syncthreads();
    for (int o = 1; o < 128; o <<= 1) {
        int a = (t >= o) ? s[t - o] : 0;
        __syncthreads();
        s[t] += a;
        __syncthreads();
    }
    if (t < NB) g_boff[t] = (t == 0) ? 0 : s[t - 1];
}

__global__ void k_scan3() {
    int t = threadIdx.x, i = blockIdx.x * 1024 + t;
    if (i < Nn) g_rowptr[i + 1] += g_boff[blockIdx.x];
    if (i == 0) g_rowptr[0] = 0;
}

__global__ void k_copy() {
    int i = blockIdx.x * blockDim.x + threadIdx.x;
    if (i < Nn) g_wptr[i] = g_rowptr[i];
}

__global__ void k_scatter(const int* __restrict__ ei) {
    int i = blockIdx.x * blockDim.x + threadIdx.x;
    if (i >= ETOT) return;
    int s, d;
    if (i < Ee) { s = ei[i]; d = ei[Ee + i]; }
    else        { s = d = i - Ee; }
    int pos = atomicAdd(&g_wptr[d], 1);
    g_src[pos] = s;
}

// ---------------- GEMM: h = X @ W  (W is [K,64], X is [Nn,K]) ----------------
template <int K, bool FROMX>
__global__ void __launch_bounds__(256) k_gemm(const float* __restrict__ Xp,
                                              const float* __restrict__ W) {
    constexpr int R = 2048 / K;   // rows per block (16 for K=128, 32 for K=64)
    constexpr int J = R / 4;      // outputs per thread
    __shared__ float sW[K * 64];
    __shared__ float sX[R * K];
    const float* X = FROMX ? Xp : g_buf;
    int t = threadIdx.x;
    for (int i = t; i < K * 64; i += 256) sW[i] = W[i];
    long row0 = (long)blockIdx.x * R;
    for (int i = t; i < R * K; i += 256) sX[i] = X[row0 * K + i];
    __syncthreads();
    int c = t & 63, rb = t >> 6;
    float acc[J];
#pragma unroll
    for (int j = 0; j < J; j++) acc[j] = 0.f;
    for (int k = 0; k < K; k++) {
        float wv = sW[k * 64 + c];
#pragma unroll
        for (int j = 0; j < J; j++) acc[j] += sX[(rb + 4 * j) * K + k] * wv;
    }
#pragma unroll
    for (int j = 0; j < J; j++) {
        long r = row0 + rb + 4 * j;
        g_feat[r * 64 + c] = acc[j];
    }
}

// ---------------- per-node attention logits ----------------
template <int HEADS>
__global__ void __launch_bounds__(256) k_al(const float* __restrict__ av,
                                            const float* __restrict__ dv) {
    int w = (blockIdx.x * blockDim.x + threadIdx.x) >> 5;
    int lane = threadIdx.x & 31;
    if (w >= Nn) return;
    float v0 = g_feat[w * 64 + lane];
    float v1 = g_feat[w * 64 + 32 + lane];
    if (HEADS == 2) {
        float s0 = v0 * av[lane],      s1 = v1 * av[32 + lane];
        float d0 = v0 * dv[lane],      d1 = v1 * dv[32 + lane];
#pragma unroll
        for (int o = 16; o; o >>= 1) {
            s0 += __shfl_xor_sync(0xffffffffu, s0, o);
            s1 += __shfl_xor_sync(0xffffffffu, s1, o);
            d0 += __shfl_xor_sync(0xffffffffu, d0, o);
            d1 += __shfl_xor_sync(0xffffffffu, d1, o);
        }
        if (lane == 0) {
            g_alsrc[w * 2] = s0; g_alsrc[w * 2 + 1] = s1;
            g_aldst[w * 2] = d0; g_aldst[w * 2 + 1] = d1;
        }
    } else {
        float s = v0 * av[lane] + v1 * av[32 + lane];
        float d = v0 * dv[lane] + v1 * dv[32 + lane];
#pragma unroll
        for (int o = 16; o; o >>= 1) {
            s += __shfl_xor_sync(0xffffffffu, s, o);
            d += __shfl_xor_sync(0xffffffffu, d, o);
        }
        if (lane == 0) { g_alsrc[w] = s; g_aldst[w] = d; }
    }
}

// ---------------- warp-per-dst softmax + aggregation ----------------
template <int HEADS, bool RELU, bool TOOUT>
__global__ void __launch_bounds__(256) k_edge(const float* __restrict__ bias,
                                              float* __restrict__ outp) {
    int w = (blockIdx.x * blockDim.x + threadIdx.x) >> 5;
    int lane = threadIdx.x & 31;
    if (w >= Nn) return;
    int beg = g_rowptr[w], end = g_rowptr[w + 1];

    float ad0, ad1 = 0.f;
    if (HEADS == 2) { ad0 = g_aldst[w * 2]; ad1 = g_aldst[w * 2 + 1]; }
    else            { ad0 = g_aldst[w]; }

    // pass 1: segment max
    float m0 = -1e30f, m1 = -1e30f;
    for (int e = beg + lane; e < end; e += 32) {
        int s = g_src[e];
        if (HEADS == 2) {
            m0 = fmaxf(m0, lrelu(g_alsrc[s * 2]     + ad0));
            m1 = fmaxf(m1, lrelu(g_alsrc[s * 2 + 1] + ad1));
        } else {
            m0 = fmaxf(m0, lrelu(g_alsrc[s] + ad0));
        }
    }
#pragma unroll
    for (int o = 16; o; o >>= 1) {
        m0 = fmaxf(m0, __shfl_xor_sync(0xffffffffu, m0, o));
        if (HEADS == 2) m1 = fmaxf(m1, __shfl_xor_sync(0xffffffffu, m1, o));
    }

    // pass 2: exp-sum
    float den0 = 0.f, den1 = 0.f;
    for (int e = beg + lane; e < end; e += 32) {
        int s = g_src[e];
        if (HEADS == 2) {
            den0 += __expf(lrelu(g_alsrc[s * 2]     + ad0) - m0);
            den1 += __expf(lrelu(g_alsrc[s * 2 + 1] + ad1) - m1);
        } else {
            den0 += __expf(lrelu(g_alsrc[s] + ad0) - m0);
        }
    }
#pragma unroll
    for (int o = 16; o; o >>= 1) {
        den0 += __shfl_xor_sync(0xffffffffu, den0, o);
        if (HEADS == 2) den1 += __shfl_xor_sync(0xffffffffu, den1, o);
    }
    float inv0 = 1.f / den0;
    float inv1 = (HEADS == 2) ? 1.f / den1 : 0.f;

    // pass 3: weighted gather (lane = channel; 256B coalesced per edge)
    float acc0 = 0.f, acc1 = 0.f;
    for (int e = beg; e < end; ++e) {
        int s = g_src[e];
        const float* fr = g_feat + (long)s * 64;
        if (HEADS == 2) {
            float a0 = __expf(lrelu(g_alsrc[s * 2]     + ad0) - m0) * inv0;
            float a1 = __expf(lrelu(g_alsrc[s * 2 + 1] + ad1) - m1) * inv1;
            acc0 += a0 * fr[lane];
            acc1 += a1 * fr[32 + lane];
        } else {
            float a = __expf(lrelu(g_alsrc[s] + ad0) - m0) * inv0;
            acc0 += a * fr[lane];
            acc1 += a * fr[32 + lane];
        }
    }

    float v0 = acc0 + bias[lane];
    float v1 = acc1 + bias[32 + lane];
    if (RELU) { v0 = fmaxf(v0, 0.f); v1 = fmaxf(v1, 0.f); }
    float* dst = TOOUT ? outp : g_buf;
    dst[(long)w * 64 + lane]      = v0;
    dst[(long)w * 64 + 32 + lane] = v1;
}

// ---------------- launch ----------------
extern "C" void kernel_launch(void* const* d_in, const int* in_sizes, int n_in,
                              void* d_out, int out_size) {
    const float* x   = (const float*)d_in[0];
    const int*   ei  = (const int*)d_in[1];   // JAX default: int64 downcast to int32
    const float* W1  = (const float*)d_in[2];
    const float* as1 = (const float*)d_in[3];
    const float* ad1 = (const float*)d_in[4];
    const float* b1  = (const float*)d_in[5];
    const float* W2  = (const float*)d_in[6];
    const float* as2 = (const float*)d_in[7];
    const float* ad2 = (const float*)d_in[8];
    const float* b2  = (const float*)d_in[9];
    const float* W3  = (const float*)d_in[10];
    const float* as3 = (const float*)d_in[11];
    const float* ad3 = (const float*)d_in[12];
    const float* b3  = (const float*)d_in[13];
    float* out = (float*)d_out;

    // CSR build
    k_zero<<<(Nn + 255) / 256, 256>>>();
    k_hist<<<(ETOT + 255) / 256, 256>>>(ei);
    k_scan1<<<NB, 1024>>>();
    k_scan2<<<1, 128>>>();
    k_scan3<<<NB, 1024>>>();
    k_copy<<<(Nn + 255) / 256, 256>>>();
    k_scatter<<<(ETOT + 255) / 256, 256>>>(ei);

    const int WG = (Nn * 32 + 255) / 256;  // one warp per node

    // layer 1: IN=128 -> 2x32, relu
    k_gemm<128, true><<<Nn / 16, 256>>>(x, W1);
    k_al<2><<<WG, 256>>>(as1, ad1);
    k_edge<2, true, false><<<WG, 256>>>(b1, nullptr);

    // layer 2: 64 -> 2x32, relu
    k_gemm<64, false><<<Nn / 32, 256>>>(nullptr, W2);
    k_al<2><<<WG, 256>>>(as2, ad2);
    k_edge<2, true, false><<<WG, 256>>>(b2, nullptr);

    // layer 3: 64 -> 1x64, no relu, write d_out
    k_gemm<64, false><<<Nn / 32, 256>>>(nullptr, W3);
    k_al<1><<<WG, 256>>>(as3, ad3);
    k_edge<1, false, true><<<WG, 256>>>(b3, out);
}

// round 4
// speedup vs baseline: 1.1748x; 1.1748x over previous
#include <cuda_runtime.h>

#define Nn 100000
#define Ee 1600000
#define ETOT 1700000   // Ee + Nn self loops
#define NB 98          // ceil(Nn/1024)

// ---------------- scratch (device globals; no allocation) ----------------
__device__ int    g_count[Nn];
__device__ int    g_rowptr[Nn + 1];
__device__ int    g_wptr[Nn];
__device__ int    g_bsum[NB];
__device__ int    g_boff[NB];
__device__ int    g_src[ETOT];
__device__ float  g_feat[Nn * 64];    // transformed features h = x @ W (row-major 64)
__device__ float  g_buf[Nn * 64];     // aggregated output (ping-pong)
__device__ float2 g_alsrc[Nn];        // per-node attention logits (src side, 2 heads)
__device__ float2 g_aldst[Nn];        // per-node attention logits (dst side, 2 heads)
__device__ float2 g_elog[ETOT];       // spill for nodes with degree > 32

__device__ __forceinline__ float lrelu(float x) { return fmaxf(x, 0.2f * x); }

// ---------------- CSR construction ----------------
__global__ void k_zero() {
    int i = blockIdx.x * blockDim.x + threadIdx.x;
    if (i < Nn) g_count[i] = 0;
}

__global__ void k_hist(const int* __restrict__ ei) {
    int i = blockIdx.x * blockDim.x + threadIdx.x;
    if (i >= ETOT) return;
    int d = (i < Ee) ? ei[Ee + i] : (i - Ee);
    atomicAdd(&g_count[d], 1);
}

__global__ void k_scan1() {
    __shared__ int s[1024];
    int t = threadIdx.x, i = blockIdx.x * 1024 + t;
    int v = (i < Nn) ? g_count[i] : 0;
    s[t] = v;
    __syncthreads();
    for (int o = 1; o < 1024; o <<= 1) {
        int a = (t >= o) ? s[t - o] : 0;
        __syncthreads();
        s[t] += a;
        __syncthreads();
    }
    if (i < Nn) g_rowptr[i + 1] = s[t];
    if (t == 1023) g_bsum[blockIdx.x] = s[t];
}

__global__ void k_scan2() {
    __shared__ int s[128];
    int t = threadIdx.x;
    s[t] = (t < NB) ? g_bsum[t] : 0;
    __syncthreads();
    for (int o = 1; o < 128; o <<= 1) {
        int a = (t >= o) ? s[t - o] : 0;
        __syncthreads();
        s[t] += a;
        __syncthreads();
    }
    if (t < NB) g_boff[t] = (t == 0) ? 0 : s[t - 1];
}

__global__ void k_scan3() {   // also produces g_wptr (= final rowptr)
    int t = threadIdx.x, i = blockIdx.x * 1024 + t;
    if (i < Nn) {
        int v = g_rowptr[i + 1] + g_boff[blockIdx.x];
        g_rowptr[i + 1] = v;
        if (i + 1 < Nn) g_wptr[i + 1] = v;
    }
    if (i == 0) { g_rowptr[0] = 0; g_wptr[0] = 0; }
}

__global__ void k_scatter(const int* __restrict__ ei) {
    int i = blockIdx.x * blockDim.x + threadIdx.x;
    if (i >= ETOT) return;
    int s, d;
    if (i < Ee) { s = ei[i]; d = ei[Ee + i]; }
    else        { s = d = i - Ee; }
    int pos = atomicAdd(&g_wptr[d], 1);
    g_src[pos] = s;
}

// ---------------- GEMM: g_feat = X @ W  (X [Nn,K], W [K,64]) ----------------
template <int K, bool FROMX>
__global__ void __launch_bounds__(256) k_gemm(const float* __restrict__ Xp,
                                              const float* __restrict__ W) {
    constexpr int R  = (K == 128) ? 16 : 32;   // rows per block
    constexpr int JR = R / 8;                  // rows per thread (2 or 4)
    __shared__ float sW[K * 64];
    __shared__ float sX[R * K];
    const float* X = FROMX ? Xp : g_buf;
    int t = threadIdx.x;
    for (int i = t; i < K * 64; i += 256) sW[i] = W[i];
    size_t row0 = (size_t)blockIdx.x * R;
    for (int i = t; i < R * K; i += 256) sX[i] = X[row0 * K + i];
    __syncthreads();

    int c = t & 31, rg = t >> 5;  // col pair (c, c+32); row group rg (warp-uniform)
    float acc[JR][2];
#pragma unroll
    for (int j = 0; j < JR; j++) { acc[j][0] = 0.f; acc[j][1] = 0.f; }

    for (int k4 = 0; k4 < K; k4 += 4) {
        float4 xv[JR];
#pragma unroll
        for (int j = 0; j < JR; j++)
            xv[j] = *(const float4*)&sX[(rg * JR + j) * K + k4];
#pragma unroll
        for (int kk = 0; kk < 4; kk++) {
            float w0 = sW[(k4 + kk) * 64 + c];
            float w1 = sW[(k4 + kk) * 64 + c + 32];
#pragma unroll
            for (int j = 0; j < JR; j++) {
                float xs = (&xv[j].x)[kk];
                acc[j][0] += xs * w0;
                acc[j][1] += xs * w1;
            }
        }
    }
#pragma unroll
    for (int j = 0; j < JR; j++) {
        size_t r = row0 + rg * JR + j;
        g_feat[r * 64 + c]      = acc[j][0];
        g_feat[r * 64 + c + 32] = acc[j][1];
    }
}

// ---------------- per-node attention logits ----------------
template <int HEADS>
__global__ void __launch_bounds__(256) k_al(const float* __restrict__ av,
                                            const float* __restrict__ dv) {
    int w = (blockIdx.x * blockDim.x + threadIdx.x) >> 5;
    int lane = threadIdx.x & 31;
    if (w >= Nn) return;
    float v0 = g_feat[w * 64 + lane];
    float v1 = g_feat[w * 64 + 32 + lane];
    if (HEADS == 2) {
        float s0 = v0 * av[lane], s1 = v1 * av[32 + lane];
        float d0 = v0 * dv[lane], d1 = v1 * dv[32 + lane];
#pragma unroll
        for (int o = 16; o; o >>= 1) {
            s0 += __shfl_xor_sync(0xffffffffu, s0, o);
            s1 += __shfl_xor_sync(0xffffffffu, s1, o);
            d0 += __shfl_xor_sync(0xffffffffu, d0, o);
            d1 += __shfl_xor_sync(0xffffffffu, d1, o);
        }
        if (lane == 0) {
            g_alsrc[w] = make_float2(s0, s1);
            g_aldst[w] = make_float2(d0, d1);
        }
    } else {
        float s = v0 * av[lane] + v1 * av[32 + lane];
        float d = v0 * dv[lane] + v1 * dv[32 + lane];
#pragma unroll
        for (int o = 16; o; o >>= 1) {
            s += __shfl_xor_sync(0xffffffffu, s, o);
            d += __shfl_xor_sync(0xffffffffu, d, o);
        }
        if (lane == 0) {
            g_alsrc[w] = make_float2(s, 0.f);
            g_aldst[w] = make_float2(d, 0.f);
        }
    }
}

// ---------------- warp-per-dst: online softmax + weighted gather ----------------
// Lane l owns channels (2l, 2l+1). Head0 = lanes 0..15, head1 = lanes 16..31.
template <int HEADS, bool RELU, bool TOOUT>
__global__ void __launch_bounds__(256) k_edge(const float* __restrict__ bias,
                                              float* __restrict__ outp) {
    int w = (blockIdx.x * blockDim.x + threadIdx.x) >> 5;
    int lane = threadIdx.x & 31;
    if (w >= Nn) return;
    int beg = g_rowptr[w], end = g_rowptr[w + 1];
    int deg = end - beg;
    bool small = (deg <= 32);

    float2 ad = g_aldst[w];

    // ---- pass 1: online softmax (max + denom in one sweep) ----
    float m0 = -1e30f, m1 = -1e30f, d0 = 0.f, d1 = 0.f;
    float lr0 = -1e30f, lr1 = -1e30f;  // this lane's edge logits (small path)
    for (int e = beg + lane; e < end; e += 32) {
        int s = g_src[e];
        float2 as = g_alsrc[s];
        float l0 = lrelu(as.x + ad.x);
        float l1 = (HEADS == 2) ? lrelu(as.y + ad.y) : 0.f;
        if (small) { lr0 = l0; lr1 = l1; }
        else       g_elog[e] = make_float2(l0, l1);
        float nm0 = fmaxf(m0, l0);
        d0 = d0 * __expf(m0 - nm0) + __expf(l0 - nm0);
        m0 = nm0;
        if (HEADS == 2) {
            float nm1 = fmaxf(m1, l1);
            d1 = d1 * __expf(m1 - nm1) + __expf(l1 - nm1);
            m1 = nm1;
        }
    }
    // warp combine
    float M0 = m0, M1 = m1;
#pragma unroll
    for (int o = 16; o; o >>= 1) {
        M0 = fmaxf(M0, __shfl_xor_sync(0xffffffffu, M0, o));
        if (HEADS == 2) M1 = fmaxf(M1, __shfl_xor_sync(0xffffffffu, M1, o));
    }
    d0 *= __expf(m0 - M0);
    if (HEADS == 2) d1 *= __expf(m1 - M1);
#pragma unroll
    for (int o = 16; o; o >>= 1) {
        d0 += __shfl_xor_sync(0xffffffffu, d0, o);
        if (HEADS == 2) d1 += __shfl_xor_sync(0xffffffffu, d1, o);
    }
    float inv0 = 1.f / d0;
    float inv1 = (HEADS == 2) ? 1.f / d1 : 0.f;
    __syncwarp();

    // per-lane head constants (receiver side)
    bool hi = (HEADS == 2) && (lane >= 16);
    float mm = hi ? M1 : M0;
    float ii = hi ? inv1 : inv0;

    // ---- pass 2: weighted feature gather, float2 per lane, 4x unrolled ----
    const float2* f2 = (const float2*)g_feat;
    float ax = 0.f, ay = 0.f;
    int e = beg;
    if (small) {
        for (; e + 4 <= end; e += 4) {
            int j = e - beg;
            int s0 = g_src[e], s1 = g_src[e + 1], s2 = g_src[e + 2], s3 = g_src[e + 3];
            // shuffle BOTH head logits; select on the receiver side
            float A0 = __shfl_sync(0xffffffffu, lr0, j);
            float A1 = __shfl_sync(0xffffffffu, lr0, j + 1);
            float A2 = __shfl_sync(0xffffffffu, lr0, j + 2);
            float A3 = __shfl_sync(0xffffffffu, lr0, j + 3);
            float L0 = A0, L1 = A1, L2 = A2, L3 = A3;
            if (HEADS == 2) {
                float B0 = __shfl_sync(0xffffffffu, lr1, j);
                float B1 = __shfl_sync(0xffffffffu, lr1, j + 1);
                float B2 = __shfl_sync(0xffffffffu, lr1, j + 2);
                float B3 = __shfl_sync(0xffffffffu, lr1, j + 3);
                if (hi) { L0 = B0; L1 = B1; L2 = B2; L3 = B3; }
            }
            float2 F0 = f2[(size_t)s0 * 32 + lane];
            float2 F1 = f2[(size_t)s1 * 32 + lane];
            float2 F2 = f2[(size_t)s2 * 32 + lane];
            float2 F3 = f2[(size_t)s3 * 32 + lane];
            float a0 = __expf(L0 - mm) * ii;
            float a1 = __expf(L1 - mm) * ii;
            float a2 = __expf(L2 - mm) * ii;
            float a3 = __expf(L3 - mm) * ii;
            ax += a0 * F0.x + a1 * F1.x + a2 * F2.x + a3 * F3.x;
            ay += a0 * F0.y + a1 * F1.y + a2 * F2.y + a3 * F3.y;
        }
        for (; e < end; ++e) {
            int j = e - beg;
            int s = g_src[e];
            float A = __shfl_sync(0xffffffffu, lr0, j);
            float L = A;
            if (HEADS == 2) {
                float B = __shfl_sync(0xffffffffu, lr1, j);
                if (hi) L = B;
            }
            float2 F = f2[(size_t)s * 32 + lane];
            float a = __expf(L - mm) * ii;
            ax += a * F.x;
            ay += a * F.y;
        }
    } else {
        for (; e + 4 <= end; e += 4) {
            int s0 = g_src[e], s1 = g_src[e + 1], s2 = g_src[e + 2], s3 = g_src[e + 3];
            float2 l0 = g_elog[e], l1 = g_elog[e + 1], l2 = g_elog[e + 2], l3 = g_elog[e + 3];
            float2 F0 = f2[(size_t)s0 * 32 + lane];
            float2 F1 = f2[(size_t)s1 * 32 + lane];
            float2 F2 = f2[(size_t)s2 * 32 + lane];
            float2 F3 = f2[(size_t)s3 * 32 + lane];
            float a0 = __expf((hi ? l0.y : l0.x) - mm) * ii;
            float a1 = __expf((hi ? l1.y : l1.x) - mm) * ii;
            float a2 = __expf((hi ? l2.y : l2.x) - mm) * ii;
            float a3 = __expf((hi ? l3.y : l3.x) - mm) * ii;
            ax += a0 * F0.x + a1 * F1.x + a2 * F2.x + a3 * F3.x;
            ay += a0 * F0.y + a1 * F1.y + a2 * F2.y + a3 * F3.y;
        }
        for (; e < end; ++e) {
            int s = g_src[e];
            float2 l = g_elog[e];
            float2 F = f2[(size_t)s * 32 + lane];
            float a = __expf((hi ? l.y : l.x) - mm) * ii;
            ax += a * F.x;
            ay += a * F.y;
        }
    }

    float2 bv = ((const float2*)bias)[lane];
    float vx = ax + bv.x, vy = ay + bv.y;
    if (RELU) { vx = fmaxf(vx, 0.f); vy = fmaxf(vy, 0.f); }
    float* dst = TOOUT ? outp : g_buf;
    ((float2*)dst)[(size_t)w * 32 + lane] = make_float2(vx, vy);
}

// ---------------- launch ----------------
extern "C" void kernel_launch(void* const* d_in, const int* in_sizes, int n_in,
                              void* d_out, int out_size) {
    const float* x   = (const float*)d_in[0];
    const int*   ei  = (const int*)d_in[1];
    const float* W1  = (const float*)d_in[2];
    const float* as1 = (const float*)d_in[3];
    const float* ad1 = (const float*)d_in[4];
    const float* b1  = (const float*)d_in[5];
    const float* W2  = (const float*)d_in[6];
    const float* as2 = (const float*)d_in[7];
    const float* ad2 = (const float*)d_in[8];
    const float* b2  = (const float*)d_in[9];
    const float* W3  = (const float*)d_in[10];
    const float* as3 = (const float*)d_in[11];
    const float* ad3 = (const float*)d_in[12];
    const float* b3  = (const float*)d_in[13];
    float* out = (float*)d_out;

    // CSR build
    k_zero<<<(Nn + 255) / 256, 256>>>();
    k_hist<<<(ETOT + 255) / 256, 256>>>(ei);
    k_scan1<<<NB, 1024>>>();
    k_scan2<<<1, 128>>>();
    k_scan3<<<NB, 1024>>>();
    k_scatter<<<(ETOT + 255) / 256, 256>>>(ei);

    const int WG = (Nn * 32 + 255) / 256;  // one warp per node

    // layer 1: IN=128 -> 2x32, relu
    k_gemm<128, true><<<Nn / 16, 256>>>(x, W1);
    k_al<2><<<WG, 256>>>(as1, ad1);
    k_edge<2, true, false><<<WG, 256>>>(b1, nullptr);

    // layer 2: 64 -> 2x32, relu
    k_gemm<64, false><<<Nn / 32, 256>>>(nullptr, W2);
    k_al<2><<<WG, 256>>>(as2, ad2);
    k_edge<2, true, false><<<WG, 256>>>(b2, nullptr);

    // layer 3: 64 -> 1x64, no relu, write d_out
    k_gemm<64, false><<<Nn / 32, 256>>>(nullptr, W3);
    k_al<1><<<WG, 256>>>(as3, ad3);
    k_edge<1, false, true><<<WG, 256>>>(b3, out);
}

// round 6
// speedup vs baseline: 1.2283x; 1.0456x over previous
#include <cuda_runtime.h>

#define Nn 100000
#define Ee 1600000
#define ETOT 1700000   // Ee + Nn self loops
#define NB 98          // ceil(Nn/1024)

// ---------------- scratch (device globals; no allocation) ----------------
__device__ int    g_count[Nn];
__device__ int    g_rowptr[Nn + 1];
__device__ int    g_wptr[Nn];
__device__ int    g_bsum[NB];
__device__ int    g_boff[NB];
__device__ int    g_src[ETOT];
__device__ float  g_feat[Nn * 64];    // transformed features h = x @ W (row-major 64)
__device__ float  g_buf[Nn * 64];     // aggregated output (ping-pong)
__device__ float2 g_alsrc[Nn];        // per-node attention logits (src side, 2 heads)
__device__ float2 g_aldst[Nn];        // per-node attention logits (dst side, 2 heads)
__device__ float2 g_elog[ETOT];       // spill for nodes with degree > 32

__device__ __forceinline__ float lrelu(float x) { return fmaxf(x, 0.2f * x); }

// ---------------- CSR construction ----------------
__global__ void k_zero() {
    int i = blockIdx.x * blockDim.x + threadIdx.x;
    if (i < Nn) g_count[i] = 0;
}

__global__ void k_hist(const int* __restrict__ ei) {
    int i = blockIdx.x * blockDim.x + threadIdx.x;
    if (i >= ETOT) return;
    int d = (i < Ee) ? ei[Ee + i] : (i - Ee);
    atomicAdd(&g_count[d], 1);
}

__global__ void k_scan1() {
    __shared__ int s[1024];
    int t = threadIdx.x, i = blockIdx.x * 1024 + t;
    int v = (i < Nn) ? g_count[i] : 0;
    s[t] = v;
    __syncthreads();
    for (int o = 1; o < 1024; o <<= 1) {
        int a = (t >= o) ? s[t - o] : 0;
        __syncthreads();
        s[t] += a;
        __syncthreads();
    }
    if (i < Nn) g_rowptr[i + 1] = s[t];
    if (t == 1023) g_bsum[blockIdx.x] = s[t];
}

__global__ void k_scan2() {
    __shared__ int s[128];
    int t = threadIdx.x;
    s[t] = (t < NB) ? g_bsum[t] : 0;
    __syncthreads();
    for (int o = 1; o < 128; o <<= 1) {
        int a = (t >= o) ? s[t - o] : 0;
        __syncthreads();
        s[t] += a;
        __syncthreads();
    }
    if (t < NB) g_boff[t] = (t == 0) ? 0 : s[t - 1];
}

__global__ void k_scan3() {   // also produces g_wptr (= final rowptr)
    int t = threadIdx.x, i = blockIdx.x * 1024 + t;
    if (i < Nn) {
        int v = g_rowptr[i + 1] + g_boff[blockIdx.x];
        g_rowptr[i + 1] = v;
        if (i + 1 < Nn) g_wptr[i + 1] = v;
    }
    if (i == 0) { g_rowptr[0] = 0; g_wptr[0] = 0; }
}

__global__ void k_scatter(const int* __restrict__ ei) {
    int i = blockIdx.x * blockDim.x + threadIdx.x;
    if (i >= ETOT) return;
    int s, d;
    if (i < Ee) { s = ei[i]; d = ei[Ee + i]; }
    else        { s = d = i - Ee; }
    int pos = atomicAdd(&g_wptr[d], 1);
    g_src[pos] = s;
}

// ---------------- GEMM + attention-logit epilogue ----------------
// g_feat = X @ W  (X [Nn,K], W [K,64]); then per-row al_src/al_dst via warp reduce.
// Warp layout: lane c owns output cols (c, c+32); warp rg owns rows rg*JR..rg*JR+JR-1.
template <int K, int HEADS, bool FROMX>
__global__ void __launch_bounds__(256) k_gemm(const float* __restrict__ Xp,
                                              const float* __restrict__ W,
                                              const float* __restrict__ av,
                                              const float* __restrict__ dv) {
    constexpr int R  = (K == 128) ? 16 : 32;   // rows per block
    constexpr int JR = R / 8;                  // rows per warp (2 or 4)
    __shared__ float sW[K * 64];
    __shared__ float sX[R * K];
    const float* X = FROMX ? Xp : g_buf;
    int t = threadIdx.x;
    for (int i = t; i < K * 64; i += 256) sW[i] = W[i];
    size_t row0 = (size_t)blockIdx.x * R;
    for (int i = t; i < R * K; i += 256) sX[i] = X[row0 * K + i];
    __syncthreads();

    int c = t & 31, rg = t >> 5;
    float acc[JR][2];
#pragma unroll
    for (int j = 0; j < JR; j++) { acc[j][0] = 0.f; acc[j][1] = 0.f; }

    for (int k4 = 0; k4 < K; k4 += 4) {
        float4 xv[JR];
#pragma unroll
        for (int j = 0; j < JR; j++)
            xv[j] = *(const float4*)&sX[(rg * JR + j) * K + k4];
#pragma unroll
        for (int kk = 0; kk < 4; kk++) {
            float w0 = sW[(k4 + kk) * 64 + c];
            float w1 = sW[(k4 + kk) * 64 + c + 32];
#pragma unroll
            for (int j = 0; j < JR; j++) {
                float xs = (&xv[j].x)[kk];
                acc[j][0] += xs * w0;
                acc[j][1] += xs * w1;
            }
        }
    }

    float a0 = av[c], a1 = av[c + 32];
    float e0 = dv[c], e1 = dv[c + 32];

#pragma unroll
    for (int j = 0; j < JR; j++) {
        size_t r = row0 + rg * JR + j;
        g_feat[r * 64 + c]      = acc[j][0];
        g_feat[r * 64 + c + 32] = acc[j][1];
        if (HEADS == 2) {
            float s0 = acc[j][0] * a0, s1 = acc[j][1] * a1;
            float d0 = acc[j][0] * e0, d1 = acc[j][1] * e1;
#pragma unroll
            for (int o = 16; o; o >>= 1) {
                s0 += __shfl_xor_sync(0xffffffffu, s0, o);
                s1 += __shfl_xor_sync(0xffffffffu, s1, o);
                d0 += __shfl_xor_sync(0xffffffffu, d0, o);
                d1 += __shfl_xor_sync(0xffffffffu, d1, o);
            }
            if (c == 0) {
                g_alsrc[r] = make_float2(s0, s1);
                g_aldst[r] = make_float2(d0, d1);
            }
        } else {
            float s = acc[j][0] * a0 + acc[j][1] * a1;
            float d = acc[j][0] * e0 + acc[j][1] * e1;
#pragma unroll
            for (int o = 16; o; o >>= 1) {
                s += __shfl_xor_sync(0xffffffffu, s, o);
                d += __shfl_xor_sync(0xffffffffu, d, o);
            }
            if (c == 0) {
                g_alsrc[r] = make_float2(s, 0.f);
                g_aldst[r] = make_float2(d, 0.f);
            }
        }
    }
}

// ---------------- warp-per-dst: online softmax + weighted gather ----------------
// Lane l owns channels (2l, 2l+1). Head0 = lanes 0..15, head1 = lanes 16..31.
template <int HEADS, bool RELU, bool TOOUT>
__global__ void __launch_bounds__(256) k_edge(const float* __restrict__ bias,
                                              float* __restrict__ outp) {
    int w = (blockIdx.x * blockDim.x + threadIdx.x) >> 5;
    int lane = threadIdx.x & 31;
    if (w >= Nn) return;
    int beg = g_rowptr[w], end = g_rowptr[w + 1];
    int deg = end - beg;
    bool small = (deg <= 32);

    float2 ad = g_aldst[w];

    // ---- pass 1: online softmax (max + denom in one sweep) ----
    float m0 = -1e30f, m1 = -1e30f, d0 = 0.f, d1 = 0.f;
    float lr0 = -1e30f, lr1 = -1e30f;  // this lane's edge logits (small path)
    for (int e = beg + lane; e < end; e += 32) {
        int s = g_src[e];
        float2 as = g_alsrc[s];
        float l0 = lrelu(as.x + ad.x);
        float l1 = (HEADS == 2) ? lrelu(as.y + ad.y) : 0.f;
        if (small) { lr0 = l0; lr1 = l1; }
        else       g_elog[e] = make_float2(l0, l1);
        float nm0 = fmaxf(m0, l0);
        d0 = d0 * __expf(m0 - nm0) + __expf(l0 - nm0);
        m0 = nm0;
        if (HEADS == 2) {
            float nm1 = fmaxf(m1, l1);
            d1 = d1 * __expf(m1 - nm1) + __expf(l1 - nm1);
            m1 = nm1;
        }
    }
    // warp combine
    float M0 = m0, M1 = m1;
#pragma unroll
    for (int o = 16; o; o >>= 1) {
        M0 = fmaxf(M0, __shfl_xor_sync(0xffffffffu, M0, o));
        if (HEADS == 2) M1 = fmaxf(M1, __shfl_xor_sync(0xffffffffu, M1, o));
    }
    d0 *= __expf(m0 - M0);
    if (HEADS == 2) d1 *= __expf(m1 - M1);
#pragma unroll
    for (int o = 16; o; o >>= 1) {
        d0 += __shfl_xor_sync(0xffffffffu, d0, o);
        if (HEADS == 2) d1 += __shfl_xor_sync(0xffffffffu, d1, o);
    }
    float inv0 = 1.f / d0;
    float inv1 = (HEADS == 2) ? 1.f / d1 : 0.f;
    __syncwarp();

    // per-lane head constants (receiver side)
    bool hi = (HEADS == 2) && (lane >= 16);
    float mm = hi ? M1 : M0;
    float ii = hi ? inv1 : inv0;

    // ---- pass 2: weighted feature gather, float2 per lane, 4x unrolled ----
    const float2* f2 = (const float2*)g_feat;
    float ax = 0.f, ay = 0.f;
    int e = beg;
    if (small) {
        for (; e + 4 <= end; e += 4) {
            int j = e - beg;
            int s0 = g_src[e], s1 = g_src[e + 1], s2 = g_src[e + 2], s3 = g_src[e + 3];
            float A0 = __shfl_sync(0xffffffffu, lr0, j);
            float A1 = __shfl_sync(0xffffffffu, lr0, j + 1);
            float A2 = __shfl_sync(0xffffffffu, lr0, j + 2);
            float A3 = __shfl_sync(0xffffffffu, lr0, j + 3);
            float L0 = A0, L1 = A1, L2 = A2, L3 = A3;
            if (HEADS == 2) {
                float B0 = __shfl_sync(0xffffffffu, lr1, j);
                float B1 = __shfl_sync(0xffffffffu, lr1, j + 1);
                float B2 = __shfl_sync(0xffffffffu, lr1, j + 2);
                float B3 = __shfl_sync(0xffffffffu, lr1, j + 3);
                if (hi) { L0 = B0; L1 = B1; L2 = B2; L3 = B3; }
            }
            float2 F0 = f2[(size_t)s0 * 32 + lane];
            float2 F1 = f2[(size_t)s1 * 32 + lane];
            float2 F2 = f2[(size_t)s2 * 32 + lane];
            float2 F3 = f2[(size_t)s3 * 32 + lane];
            float a0 = __expf(L0 - mm) * ii;
            float a1 = __expf(L1 - mm) * ii;
            float a2 = __expf(L2 - mm) * ii;
            float a3 = __expf(L3 - mm) * ii;
            ax += a0 * F0.x + a1 * F1.x + a2 * F2.x + a3 * F3.x;
            ay += a0 * F0.y + a1 * F1.y + a2 * F2.y + a3 * F3.y;
        }
        for (; e < end; ++e) {
            int j = e - beg;
            int s = g_src[e];
            float A = __shfl_sync(0xffffffffu, lr0, j);
            float L = A;
            if (HEADS == 2) {
                float B = __shfl_sync(0xffffffffu, lr1, j);
                if (hi) L = B;
            }
            float2 F = f2[(size_t)s * 32 + lane];
            float a = __expf(L - mm) * ii;
            ax += a * F.x;
            ay += a * F.y;
        }
    } else {
        for (; e + 4 <= end; e += 4) {
            int s0 = g_src[e], s1 = g_src[e + 1], s2 = g_src[e + 2], s3 = g_src[e + 3];
            float2 l0 = g_elog[e], l1 = g_elog[e + 1], l2 = g_elog[e + 2], l3 = g_elog[e + 3];
            float2 F0 = f2[(size_t)s0 * 32 + lane];
            float2 F1 = f2[(size_t)s1 * 32 + lane];
            float2 F2 = f2[(size_t)s2 * 32 + lane];
            float2 F3 = f2[(size_t)s3 * 32 + lane];
            float a0 = __expf((hi ? l0.y : l0.x) - mm) * ii;
            float a1 = __expf((hi ? l1.y : l1.x) - mm) * ii;
            float a2 = __expf((hi ? l2.y : l2.x) - mm) * ii;
            float a3 = __expf((hi ? l3.y : l3.x) - mm) * ii;
            ax += a0 * F0.x + a1 * F1.x + a2 * F2.x + a3 * F3.x;
            ay += a0 * F0.y + a1 * F1.y + a2 * F2.y + a3 * F3.y;
        }
        for (; e < end; ++e) {
            int s = g_src[e];
            float2 l = g_elog[e];
            float2 F = f2[(size_t)s * 32 + lane];
            float a = __expf((hi ? l.y : l.x) - mm) * ii;
            ax += a * F.x;
            ay += a * F.y;
        }
    }

    float2 bv = ((const float2*)bias)[lane];
    float vx = ax + bv.x, vy = ay + bv.y;
    if (RELU) { vx = fmaxf(vx, 0.f); vy = fmaxf(vy, 0.f); }
    float* dst = TOOUT ? outp : g_buf;
    ((float2*)dst)[(size_t)w * 32 + lane] = make_float2(vx, vy);
}

// ---------------- launch ----------------
extern "C" void kernel_launch(void* const* d_in, const int* in_sizes, int n_in,
                              void* d_out, int out_size) {
    const float* x   = (const float*)d_in[0];
    const int*   ei  = (const int*)d_in[1];
    const float* W1  = (const float*)d_in[2];
    const float* as1 = (const float*)d_in[3];
    const float* ad1 = (const float*)d_in[4];
    const float* b1  = (const float*)d_in[5];
    const float* W2  = (const float*)d_in[6];
    const float* as2 = (const float*)d_in[7];
    const float* ad2 = (const float*)d_in[8];
    const float* b2  = (const float*)d_in[9];
    const float* W3  = (const float*)d_in[10];
    const float* as3 = (const float*)d_in[11];
    const float* ad3 = (const float*)d_in[12];
    const float* b3  = (const float*)d_in[13];
    float* out = (float*)d_out;

    // Side stream + events for the CSR branch (host objects only; created per
    // call — kernel_launch runs exactly twice, so the leak is two objects).
    cudaStream_t sa;
    cudaEvent_t e0, e1;
    cudaStreamCreateWithFlags(&sa, cudaStreamNonBlocking);
    cudaEventCreateWithFlags(&e0, cudaEventDisableTiming);
    cudaEventCreateWithFlags(&e1, cudaEventDisableTiming);

    // fork: CSR build runs concurrently with layer-1 GEMM
    cudaEventRecord(e0, 0);
    cudaStreamWaitEvent(sa, e0, 0);
    k_zero<<<(Nn + 255) / 256, 256, 0, sa>>>();
    k_hist<<<(ETOT + 255) / 256, 256, 0, sa>>>(ei);
    k_scan1<<<NB, 1024, 0, sa>>>();
    k_scan2<<<1, 128, 0, sa>>>();
    k_scan3<<<NB, 1024, 0, sa>>>();
    k_scatter<<<(ETOT + 255) / 256, 256, 0, sa>>>(ei);
    cudaEventRecord(e1, sa);

    const int WG = (Nn * 32 + 255) / 256;  // one warp per node

    // layer 1: IN=128 -> 2x32, relu (GEMM runs parallel to CSR build)
    k_gemm<128, 2, true><<<Nn / 16, 256>>>(x, W1, as1, ad1);
    cudaStreamWaitEvent(0, e1, 0);   // join: edge kernel needs CSR
    k_edge<2, true, false><<<WG, 256>>>(b1, nullptr);

    // layer 2: 64 -> 2x32, relu
    k_gemm<64, 2, false><<<Nn / 32, 256>>>(nullptr, W2, as2, ad2);
    k_edge<2, true, false><<<WG, 256>>>(b2, nullptr);

    // layer 3: 64 -> 1x64, no relu, write d_out
    k_gemm<64, 1, false><<<Nn / 32, 256>>>(nullptr, W3, as3, ad3);
    k_edge<1, false, true><<<WG, 256>>>(b3, out);
}

// round 7
// speedup vs baseline: 1.3408x; 1.0915x over previous
#include <cuda_runtime.h>

#define Nn 100000
#define Ee 1600000
#define ETOT 1700000   // Ee + Nn self loops
#define NB 98          // ceil(Nn/1024)

// ---------------- scratch (device globals; no allocation) ----------------
__device__ int    g_count[Nn];
__device__ int    g_rowptr[Nn + 1];
__device__ int    g_wptr[Nn];
__device__ int    g_bsum[NB];
__device__ int    g_boff[NB];
__device__ int    g_src[ETOT];
__device__ float  g_feat[Nn * 64];    // transformed features h = x @ W (row-major 64)
__device__ float  g_buf[Nn * 64];     // aggregated output (ping-pong)
__device__ float2 g_alsrc[Nn];        // per-node attention logits (src side, 2 heads)
__device__ float2 g_aldst[Nn];        // per-node attention logits (dst side, 2 heads)
__device__ float2 g_elog[ETOT];       // spill for nodes with degree > 32

__device__ __forceinline__ float lrelu(float x) { return fmaxf(x, 0.2f * x); }

// ---------------- CSR construction ----------------
__global__ void k_zero() {
    int i = blockIdx.x * blockDim.x + threadIdx.x;
    if (i < Nn) g_count[i] = 0;
}

__global__ void k_hist(const int* __restrict__ ei) {
    int i = blockIdx.x * blockDim.x + threadIdx.x;
    if (i >= ETOT) return;
    int d = (i < Ee) ? ei[Ee + i] : (i - Ee);
    atomicAdd(&g_count[d], 1);
}

__global__ void k_scan1() {
    __shared__ int s[1024];
    int t = threadIdx.x, i = blockIdx.x * 1024 + t;
    int v = (i < Nn) ? g_count[i] : 0;
    s[t] = v;
    __syncthreads();
    for (int o = 1; o < 1024; o <<= 1) {
        int a = (t >= o) ? s[t - o] : 0;
        __syncthreads();
        s[t] += a;
        __syncthreads();
    }
    if (i < Nn) g_rowptr[i + 1] = s[t];
    if (t == 1023) g_bsum[blockIdx.x] = s[t];
}

__global__ void k_scan2() {
    __shared__ int s[128];
    int t = threadIdx.x;
    s[t] = (t < NB) ? g_bsum[t] : 0;
    __syncthreads();
    for (int o = 1; o < 128; o <<= 1) {
        int a = (t >= o) ? s[t - o] : 0;
        __syncthreads();
        s[t] += a;
        __syncthreads();
    }
    if (t < NB) g_boff[t] = (t == 0) ? 0 : s[t - 1];
}

__global__ void k_scan3() {   // also produces g_wptr (= final rowptr)
    int t = threadIdx.x, i = blockIdx.x * 1024 + t;
    if (i < Nn) {
        int v = g_rowptr[i + 1] + g_boff[blockIdx.x];
        g_rowptr[i + 1] = v;
        if (i + 1 < Nn) g_wptr[i + 1] = v;
    }
    if (i == 0) { g_rowptr[0] = 0; g_wptr[0] = 0; }
}

__global__ void k_scatter(const int* __restrict__ ei) {
    int i = blockIdx.x * blockDim.x + threadIdx.x;
    if (i >= ETOT) return;
    int s, d;
    if (i < Ee) { s = ei[i]; d = ei[Ee + i]; }
    else        { s = d = i - Ee; }
    int pos = atomicAdd(&g_wptr[d], 1);
    g_src[pos] = s;
}

// ---------------- GEMM + attention-logit epilogue ----------------
template <int K, int HEADS, bool FROMX>
__global__ void __launch_bounds__(256) k_gemm(const float* __restrict__ Xp,
                                              const float* __restrict__ W,
                                              const float* __restrict__ av,
                                              const float* __restrict__ dv) {
    constexpr int R  = (K == 128) ? 16 : 32;   // rows per block
    constexpr int JR = R / 8;                  // rows per warp (2 or 4)
    __shared__ float sW[K * 64];
    __shared__ float sX[R * K];
    const float* X = FROMX ? Xp : g_buf;
    int t = threadIdx.x;
    for (int i = t; i < K * 64; i += 256) sW[i] = W[i];
    size_t row0 = (size_t)blockIdx.x * R;
    for (int i = t; i < R * K; i += 256) sX[i] = X[row0 * K + i];
    __syncthreads();

    int c = t & 31, rg = t >> 5;
    float acc[JR][2];
#pragma unroll
    for (int j = 0; j < JR; j++) { acc[j][0] = 0.f; acc[j][1] = 0.f; }

    for (int k4 = 0; k4 < K; k4 += 4) {
        float4 xv[JR];
#pragma unroll
        for (int j = 0; j < JR; j++)
            xv[j] = *(const float4*)&sX[(rg * JR + j) * K + k4];
#pragma unroll
        for (int kk = 0; kk < 4; kk++) {
            float w0 = sW[(k4 + kk) * 64 + c];
            float w1 = sW[(k4 + kk) * 64 + c + 32];
#pragma unroll
            for (int j = 0; j < JR; j++) {
                float xs = (&xv[j].x)[kk];
                acc[j][0] += xs * w0;
                acc[j][1] += xs * w1;
            }
        }
    }

    float a0 = av[c], a1 = av[c + 32];
    float e0 = dv[c], e1 = dv[c + 32];

#pragma unroll
    for (int j = 0; j < JR; j++) {
        size_t r = row0 + rg * JR + j;
        g_feat[r * 64 + c]      = acc[j][0];
        g_feat[r * 64 + c + 32] = acc[j][1];
        if (HEADS == 2) {
            float s0 = acc[j][0] * a0, s1 = acc[j][1] * a1;
            float d0 = acc[j][0] * e0, d1 = acc[j][1] * e1;
#pragma unroll
            for (int o = 16; o; o >>= 1) {
                s0 += __shfl_xor_sync(0xffffffffu, s0, o);
                s1 += __shfl_xor_sync(0xffffffffu, s1, o);
                d0 += __shfl_xor_sync(0xffffffffu, d0, o);
                d1 += __shfl_xor_sync(0xffffffffu, d1, o);
            }
            if (c == 0) {
                g_alsrc[r] = make_float2(s0, s1);
                g_aldst[r] = make_float2(d0, d1);
            }
        } else {
            float s = acc[j][0] * a0 + acc[j][1] * a1;
            float d = acc[j][0] * e0 + acc[j][1] * e1;
#pragma unroll
            for (int o = 16; o; o >>= 1) {
                s += __shfl_xor_sync(0xffffffffu, s, o);
                d += __shfl_xor_sync(0xffffffffu, d, o);
            }
            if (c == 0) {
                g_alsrc[r] = make_float2(s, 0.f);
                g_aldst[r] = make_float2(d, 0.f);
            }
        }
    }
}

// ---------------- warp-per-dst: online softmax + weighted gather ----------------
// Pass 1: lane = edge (striped). Pass 2: half-warp per edge, lane = float4 of 4
// channels. Lanes 0-15 even edges, 16-31 odd edges; combined via shfl_xor(16).
template <int HEADS, bool RELU, bool TOOUT>
__global__ void __launch_bounds__(256) k_edge(const float* __restrict__ bias,
                                              float* __restrict__ outp) {
    int w = (blockIdx.x * blockDim.x + threadIdx.x) >> 5;
    int lane = threadIdx.x & 31;
    if (w >= Nn) return;
    int beg = g_rowptr[w], end = g_rowptr[w + 1];
    int deg = end - beg;
    bool small = (deg <= 32);

    float2 ad = g_aldst[w];

    // ---- pass 1: online softmax (max + denom in one sweep) ----
    float m0 = -1e30f, m1 = -1e30f, d0 = 0.f, d1 = 0.f;
    float lr0 = -1e30f, lr1 = -1e30f;  // this lane's edge logits (small path)
    for (int e = beg + lane; e < end; e += 32) {
        int s = g_src[e];
        float2 as = g_alsrc[s];
        float l0 = lrelu(as.x + ad.x);
        float l1 = (HEADS == 2) ? lrelu(as.y + ad.y) : 0.f;
        if (small) { lr0 = l0; lr1 = l1; }
        else       g_elog[e] = make_float2(l0, l1);
        float nm0 = fmaxf(m0, l0);
        d0 = d0 * __expf(m0 - nm0) + __expf(l0 - nm0);
        m0 = nm0;
        if (HEADS == 2) {
            float nm1 = fmaxf(m1, l1);
            d1 = d1 * __expf(m1 - nm1) + __expf(l1 - nm1);
            m1 = nm1;
        }
    }
    float M0 = m0, M1 = m1;
#pragma unroll
    for (int o = 16; o; o >>= 1) {
        M0 = fmaxf(M0, __shfl_xor_sync(0xffffffffu, M0, o));
        if (HEADS == 2) M1 = fmaxf(M1, __shfl_xor_sync(0xffffffffu, M1, o));
    }
    d0 *= __expf(m0 - M0);
    if (HEADS == 2) d1 *= __expf(m1 - M1);
#pragma unroll
    for (int o = 16; o; o >>= 1) {
        d0 += __shfl_xor_sync(0xffffffffu, d0, o);
        if (HEADS == 2) d1 += __shfl_xor_sync(0xffffffffu, d1, o);
    }
    float inv0 = 1.f / d0;
    float inv1 = (HEADS == 2) ? 1.f / d1 : 0.f;
    __syncwarp();

    // ---- pass 2: half-warp per edge, float4 channels ----
    int sub = lane >> 4;     // 0 = even edges, 1 = odd edges
    int q   = lane & 15;     // channel group: floats 4q..4q+3
    bool hi = (HEADS == 2) && (q >= 8);   // channels >= 32 -> head 1
    float mm = hi ? M1 : M0;
    float ii = hi ? inv1 : inv0;

    const float4* f4 = (const float4*)g_feat;
    float4 acc = make_float4(0.f, 0.f, 0.f, 0.f);
    int e = beg;
    if (small) {
        for (; e + 4 <= end; e += 4) {
            int j0 = e - beg + sub, j1 = j0 + 2;
            int s0 = g_src[e + sub], s1 = g_src[e + 2 + sub];
            float A0 = __shfl_sync(0xffffffffu, lr0, j0);
            float A1 = __shfl_sync(0xffffffffu, lr0, j1);
            float L0 = A0, L1 = A1;
            if (HEADS == 2) {
                float B0 = __shfl_sync(0xffffffffu, lr1, j0);
                float B1 = __shfl_sync(0xffffffffu, lr1, j1);
                if (hi) { L0 = B0; L1 = B1; }
            }
            float4 F0 = f4[(size_t)s0 * 16 + q];
            float4 F1 = f4[(size_t)s1 * 16 + q];
            float a0 = __expf(L0 - mm) * ii;
            float a1 = __expf(L1 - mm) * ii;
            acc.x += a0 * F0.x + a1 * F1.x;
            acc.y += a0 * F0.y + a1 * F1.y;
            acc.z += a0 * F0.z + a1 * F1.z;
            acc.w += a0 * F0.w + a1 * F1.w;
        }
        for (; e < end; e += 2) {
            int idx = e + sub;
            bool v = idx < end;
            int j = (idx - beg) & 31;
            int ss = g_src[v ? idx : (end - 1)];
            float A = __shfl_sync(0xffffffffu, lr0, j);
            float L = A;
            if (HEADS == 2) {
                float B = __shfl_sync(0xffffffffu, lr1, j);
                if (hi) L = B;
            }
            float4 F = f4[(size_t)ss * 16 + q];
            float a = v ? __expf(L - mm) * ii : 0.f;
            acc.x += a * F.x; acc.y += a * F.y;
            acc.z += a * F.z; acc.w += a * F.w;
        }
    } else {
        for (; e + 4 <= end; e += 4) {
            int s0 = g_src[e + sub], s1 = g_src[e + 2 + sub];
            float2 l0 = g_elog[e + sub], l1 = g_elog[e + 2 + sub];
            float4 F0 = f4[(size_t)s0 * 16 + q];
            float4 F1 = f4[(size_t)s1 * 16 + q];
            float a0 = __expf((hi ? l0.y : l0.x) - mm) * ii;
            float a1 = __expf((hi ? l1.y : l1.x) - mm) * ii;
            acc.x += a0 * F0.x + a1 * F1.x;
            acc.y += a0 * F0.y + a1 * F1.y;
            acc.z += a0 * F0.z + a1 * F1.z;
            acc.w += a0 * F0.w + a1 * F1.w;
        }
        for (; e < end; e += 2) {
            int idx = e + sub;
            bool v = idx < end;
            int ix = v ? idx : (end - 1);
            int ss = g_src[ix];
            float2 l = g_elog[ix];
            float4 F = f4[(size_t)ss * 16 + q];
            float a = v ? __expf((hi ? l.y : l.x) - mm) * ii : 0.f;
            acc.x += a * F.x; acc.y += a * F.y;
            acc.z += a * F.z; acc.w += a * F.w;
        }
    }

    // combine even/odd halves
    acc.x += __shfl_xor_sync(0xffffffffu, acc.x, 16);
    acc.y += __shfl_xor_sync(0xffffffffu, acc.y, 16);
    acc.z += __shfl_xor_sync(0xffffffffu, acc.z, 16);
    acc.w += __shfl_xor_sync(0xffffffffu, acc.w, 16);

    if (lane < 16) {
        float4 bv = ((const float4*)bias)[q];
        float4 r;
        r.x = acc.x + bv.x; r.y = acc.y + bv.y;
        r.z = acc.z + bv.z; r.w = acc.w + bv.w;
        if (RELU) {
            r.x = fmaxf(r.x, 0.f); r.y = fmaxf(r.y, 0.f);
            r.z = fmaxf(r.z, 0.f); r.w = fmaxf(r.w, 0.f);
        }
        float* dst = TOOUT ? outp : g_buf;
        ((float4*)dst)[(size_t)w * 16 + q] = r;
    }
}

// ---------------- launch ----------------
extern "C" void kernel_launch(void* const* d_in, const int* in_sizes, int n_in,
                              void* d_out, int out_size) {
    const float* x   = (const float*)d_in[0];
    const int*   ei  = (const int*)d_in[1];
    const float* W1  = (const float*)d_in[2];
    const float* as1 = (const float*)d_in[3];
    const float* ad1 = (const float*)d_in[4];
    const float* b1  = (const float*)d_in[5];
    const float* W2  = (const float*)d_in[6];
    const float* as2 = (const float*)d_in[7];
    const float* ad2 = (const float*)d_in[8];
    const float* b2  = (const float*)d_in[9];
    const float* W3  = (const float*)d_in[10];
    const float* as3 = (const float*)d_in[11];
    const float* ad3 = (const float*)d_in[12];
    const float* b3  = (const float*)d_in[13];
    float* out = (float*)d_out;

    cudaStream_t sa;
    cudaEvent_t e0, e1;
    cudaStreamCreateWithFlags(&sa, cudaStreamNonBlocking);
    cudaEventCreateWithFlags(&e0, cudaEventDisableTiming);
    cudaEventCreateWithFlags(&e1, cudaEventDisableTiming);

    // fork: CSR build runs concurrently with layer-1 GEMM.
    // Submission order puts k_gemm<128> 4th so ncu (-s 5 -c 1) profiles it.
    cudaEventRecord(e0, 0);
    cudaStreamWaitEvent(sa, e0, 0);
    k_zero<<<(Nn + 255) / 256, 256, 0, sa>>>();                 // 1
    k_hist<<<(ETOT + 255) / 256, 256, 0, sa>>>(ei);             // 2
    k_scan1<<<NB, 1024, 0, sa>>>();                             // 3
    k_gemm<128, 2, true><<<Nn / 16, 256>>>(x, W1, as1, ad1);    // 4 <- profile target
    k_scan2<<<1, 128, 0, sa>>>();                               // 5
    k_scan3<<<NB, 1024, 0, sa>>>();                             // 6
    k_scatter<<<(ETOT + 255) / 256, 256, 0, sa>>>(ei);          // 7
    cudaEventRecord(e1, sa);

    const int WG = (Nn * 32 + 255) / 256;  // one warp per node

    cudaStreamWaitEvent(0, e1, 0);   // join: edge kernel needs CSR
    k_edge<2, true, false><<<WG, 256>>>(b1, nullptr);

    // layer 2: 64 -> 2x32, relu
    k_gemm<64, 2, false><<<Nn / 32, 256>>>(nullptr, W2, as2, ad2);
    k_edge<2, true, false><<<WG, 256>>>(b2, nullptr);

    // layer 3: 64 -> 1x64, no relu, write d_out
    k_gemm<64, 1, false><<<Nn / 32, 256>>>(nullptr, W3, as3, ad3);
    k_edge<1, false, true><<<WG, 256>>>(b3, out);
}

// round 9
// speedup vs baseline: 1.7954x; 1.3391x over previous
#include <cuda_runtime.h>

#define Nn 100000
#define Ee 1600000
#define ETOT 1700000   // Ee + Nn self loops
#define NB 98          // ceil(Nn/1024)

// ---------------- scratch (device globals; no allocation) ----------------
__device__ int    g_count[Nn];
__device__ int    g_rowptr[Nn + 1];
__device__ int    g_wptr[Nn];
__device__ int    g_bsum[NB];
__device__ int    g_boff[NB];
__device__ int    g_src[ETOT];
__device__ float  g_feat[Nn * 64];    // transformed features h = x @ W (row-major 64)
__device__ float  g_buf[Nn * 64];     // aggregated output (ping-pong)
__device__ float2 g_alsrc[Nn];        // per-node attention logits (src side, 2 heads)
__device__ float2 g_aldst[Nn];        // per-node attention logits (dst side, 2 heads)
__device__ float2 g_elog[ETOT];       // spill for nodes with degree > 32

__device__ __forceinline__ float lrelu(float x) { return fmaxf(x, 0.2f * x); }

// ---------------- CSR construction ----------------
__global__ void k_zero() {
    int i = blockIdx.x * blockDim.x + threadIdx.x;
    if (i < Nn) g_count[i] = 0;
}

__global__ void k_hist(const int* __restrict__ ei) {
    int i = blockIdx.x * blockDim.x + threadIdx.x;
    if (i >= ETOT) return;
    int d = (i < Ee) ? ei[Ee + i] : (i - Ee);
    atomicAdd(&g_count[d], 1);
}

__global__ void k_scan1() {
    __shared__ int s[1024];
    int t = threadIdx.x, i = blockIdx.x * 1024 + t;
    int v = (i < Nn) ? g_count[i] : 0;
    s[t] = v;
    __syncthreads();
    for (int o = 1; o < 1024; o <<= 1) {
        int a = (t >= o) ? s[t - o] : 0;
        __syncthreads();
        s[t] += a;
        __syncthreads();
    }
    if (i < Nn) g_rowptr[i + 1] = s[t];
    if (t == 1023) g_bsum[blockIdx.x] = s[t];
}

__global__ void k_scan2() {
    __shared__ int s[128];
    int t = threadIdx.x;
    s[t] = (t < NB) ? g_bsum[t] : 0;
    __syncthreads();
    for (int o = 1; o < 128; o <<= 1) {
        int a = (t >= o) ? s[t - o] : 0;
        __syncthreads();
        s[t] += a;
        __syncthreads();
    }
    if (t < NB) g_boff[t] = (t == 0) ? 0 : s[t - 1];
}

__global__ void k_scan3() {   // also produces g_wptr (= final rowptr)
    int t = threadIdx.x, i = blockIdx.x * 1024 + t;
    if (i < Nn) {
        int v = g_rowptr[i + 1] + g_boff[blockIdx.x];
        g_rowptr[i + 1] = v;
        if (i + 1 < Nn) g_wptr[i + 1] = v;
    }
    if (i == 0) { g_rowptr[0] = 0; g_wptr[0] = 0; }
}

__global__ void k_scatter(const int* __restrict__ ei) {
    int i = blockIdx.x * blockDim.x + threadIdx.x;
    if (i >= ETOT) return;
    int s, d;
    if (i < Ee) { s = ei[i]; d = ei[Ee + i]; }
    else        { s = d = i - Ee; }
    int pos = atomicAdd(&g_wptr[d], 1);
    g_src[pos] = s;
}

// ---------------- GEMM (8x8 register tile) + attention-logit epilogue --------
// Block tile: 256 rows x 64 cols, K chunked by 32. Thread (cx = t&7, ry = t>>3)
// computes rows ry*8..+7, cols cx*8..+7. Per k: 64 FMA vs 8 scalar LDS (bcast,
// stride-37 pad, conflict-free) + 2 LDS.128 (bcast). FMA-pipe bound.
template <int K, int HEADS, bool FROMX>
__global__ void __launch_bounds__(256) k_gemm(const float* __restrict__ Xp,
                                              const float* __restrict__ W,
                                              const float* __restrict__ av,
                                              const float* __restrict__ dv) {
    constexpr int KC  = 32;
    constexpr int STR = KC + 5;            // 37: conflict-free scalar LDS
    __shared__ float sX[256 * STR];        // 37888 B
    __shared__ float sW[KC * 64];          // 8192 B
    const float* X = FROMX ? Xp : g_buf;
    int t = threadIdx.x;
    int row0 = blockIdx.x * 256;
    int cx = t & 7;        // column group: cols cx*8..cx*8+7
    int ry = t >> 3;       // row group: rows ry*8..ry*8+7

    float acc[8][8];
#pragma unroll
    for (int i = 0; i < 8; i++)
#pragma unroll
        for (int j = 0; j < 8; j++) acc[i][j] = 0.f;

    for (int k0 = 0; k0 < K; k0 += KC) {
        // load X chunk (256 rows x 32 k) : 2048 float4, 8 per thread
#pragma unroll
        for (int i = 0; i < 8; i++) {
            int idx = t + i * 256;
            int r = idx >> 3;
            int k4 = (idx & 7) << 2;
            int grow = row0 + r;
            float4 v = make_float4(0.f, 0.f, 0.f, 0.f);
            if (grow < Nn) v = *(const float4*)&X[(size_t)grow * K + k0 + k4];
            sX[r * STR + k4]     = v.x;
            sX[r * STR + k4 + 1] = v.y;
            sX[r * STR + k4 + 2] = v.z;
            sX[r * STR + k4 + 3] = v.w;
        }
        // load W chunk (32 x 64) : 512 float4, 2 per thread
#pragma unroll
        for (int i = 0; i < 2; i++) {
            int idx = t + i * 256;
            int k = idx >> 4;
            int c4 = (idx & 15) << 2;
            *(float4*)&sW[k * 64 + c4] = *(const float4*)&W[(size_t)(k0 + k) * 64 + c4];
        }
        __syncthreads();

#pragma unroll
        for (int k = 0; k < KC; k++) {
            float xr[8];
#pragma unroll
            for (int i = 0; i < 8; i++) xr[i] = sX[(ry * 8 + i) * STR + k];
            float4 w0 = *(const float4*)&sW[k * 64 + cx * 8];
            float4 w1 = *(const float4*)&sW[k * 64 + cx * 8 + 4];
#pragma unroll
            for (int i = 0; i < 8; i++) {
                acc[i][0] += xr[i] * w0.x;
                acc[i][1] += xr[i] * w0.y;
                acc[i][2] += xr[i] * w0.z;
                acc[i][3] += xr[i] * w0.w;
                acc[i][4] += xr[i] * w1.x;
                acc[i][5] += xr[i] * w1.y;
                acc[i][6] += xr[i] * w1.z;
                acc[i][7] += xr[i] * w1.w;
            }
        }
        __syncthreads();
    }

    // epilogue: store feat + per-row attention logits
    float4 avA = *(const float4*)&av[cx * 8];
    float4 avB = *(const float4*)&av[cx * 8 + 4];
    float4 dvA = *(const float4*)&dv[cx * 8];
    float4 dvB = *(const float4*)&dv[cx * 8 + 4];

#pragma unroll
    for (int i = 0; i < 8; i++) {
        int grow = row0 + ry * 8 + i;
        bool ok = (grow < Nn);
        if (ok) {
            *(float4*)&g_feat[(size_t)grow * 64 + cx * 8] =
                make_float4(acc[i][0], acc[i][1], acc[i][2], acc[i][3]);
            *(float4*)&g_feat[(size_t)grow * 64 + cx * 8 + 4] =
                make_float4(acc[i][4], acc[i][5], acc[i][6], acc[i][7]);
        }
        float ps = acc[i][0] * avA.x + acc[i][1] * avA.y + acc[i][2] * avA.z + acc[i][3] * avA.w
                 + acc[i][4] * avB.x + acc[i][5] * avB.y + acc[i][6] * avB.z + acc[i][7] * avB.w;
        float pd = acc[i][0] * dvA.x + acc[i][1] * dvA.y + acc[i][2] * dvA.z + acc[i][3] * dvA.w
                 + acc[i][4] * dvB.x + acc[i][5] * dvB.y + acc[i][6] * dvB.z + acc[i][7] * dvB.w;
        // reduce within 4-lane subgroup (cx 0-3 = head0 cols, cx 4-7 = head1 cols)
        ps += __shfl_xor_sync(0xffffffffu, ps, 1);
        ps += __shfl_xor_sync(0xffffffffu, ps, 2);
        pd += __shfl_xor_sync(0xffffffffu, pd, 1);
        pd += __shfl_xor_sync(0xffffffffu, pd, 2);
        if (HEADS == 2) {
            float ps1 = __shfl_xor_sync(0xffffffffu, ps, 4);  // other head's sum
            float pd1 = __shfl_xor_sync(0xffffffffu, pd, 4);
            if (cx == 0 && ok) {
                g_alsrc[grow] = make_float2(ps, ps1);
                g_aldst[grow] = make_float2(pd, pd1);
            }
        } else {
            ps += __shfl_xor_sync(0xffffffffu, ps, 4);
            pd += __shfl_xor_sync(0xffffffffu, pd, 4);
            if (cx == 0 && ok) {
                g_alsrc[grow] = make_float2(ps, 0.f);
                g_aldst[grow] = make_float2(pd, 0.f);
            }
        }
    }
}

// ---------------- warp-per-dst: online softmax + weighted gather ----------------
// Pass 1: lane = edge (striped). Pass 2: half-warp per edge, lane = float4 of 4
// channels. Lanes 0-15 even edges, 16-31 odd edges; combined via shfl_xor(16).
template <int HEADS, bool RELU, bool TOOUT>
__global__ void __launch_bounds__(256) k_edge(const float* __restrict__ bias,
                                              float* __restrict__ outp) {
    int w = (blockIdx.x * blockDim.x + threadIdx.x) >> 5;
    int lane = threadIdx.x & 31;
    if (w >= Nn) return;
    int beg = g_rowptr[w], end = g_rowptr[w + 1];
    int deg = end - beg;
    bool small = (deg <= 32);

    float2 ad = g_aldst[w];

    // ---- pass 1: online softmax (max + denom in one sweep) ----
    float m0 = -1e30f, m1 = -1e30f, d0 = 0.f, d1 = 0.f;
    float lr0 = -1e30f, lr1 = -1e30f;  // this lane's edge logits (small path)
    for (int e = beg + lane; e < end; e += 32) {
        int s = g_src[e];
        float2 as = g_alsrc[s];
        float l0 = lrelu(as.x + ad.x);
        float l1 = (HEADS == 2) ? lrelu(as.y + ad.y) : 0.f;
        if (small) { lr0 = l0; lr1 = l1; }
        else       g_elog[e] = make_float2(l0, l1);
        float nm0 = fmaxf(m0, l0);
        d0 = d0 * __expf(m0 - nm0) + __expf(l0 - nm0);
        m0 = nm0;
        if (HEADS == 2) {
            float nm1 = fmaxf(m1, l1);
            d1 = d1 * __expf(m1 - nm1) + __expf(l1 - nm1);
            m1 = nm1;
        }
    }
    float M0 = m0, M1 = m1;
#pragma unroll
    for (int o = 16; o; o >>= 1) {
        M0 = fmaxf(M0, __shfl_xor_sync(0xffffffffu, M0, o));
        if (HEADS == 2) M1 = fmaxf(M1, __shfl_xor_sync(0xffffffffu, M1, o));
    }
    d0 *= __expf(m0 - M0);
    if (HEADS == 2) d1 *= __expf(m1 - M1);
#pragma unroll
    for (int o = 16; o; o >>= 1) {
        d0 += __shfl_xor_sync(0xffffffffu, d0, o);
        if (HEADS == 2) d1 += __shfl_xor_sync(0xffffffffu, d1, o);
    }
    float inv0 = 1.f / d0;
    float inv1 = (HEADS == 2) ? 1.f / d1 : 0.f;
    __syncwarp();

    // ---- pass 2: half-warp per edge, float4 channels ----
    int sub = lane >> 4;     // 0 = even edges, 1 = odd edges
    int q   = lane & 15;     // channel group: floats 4q..4q+3
    bool hi = (HEADS == 2) && (q >= 8);   // channels >= 32 -> head 1
    float mm = hi ? M1 : M0;
    float ii = hi ? inv1 : inv0;

    const float4* f4 = (const float4*)g_feat;
    float4 acc = make_float4(0.f, 0.f, 0.f, 0.f);
    int e = beg;
    if (small) {
        for (; e + 4 <= end; e += 4) {
            int j0 = e - beg + sub, j1 = j0 + 2;
            int s0 = g_src[e + sub], s1 = g_src[e + 2 + sub];
            float A0 = __shfl_sync(0xffffffffu, lr0, j0);
            float A1 = __shfl_sync(0xffffffffu, lr0, j1);
            float L0 = A0, L1 = A1;
            if (HEADS == 2) {
                float B0 = __shfl_sync(0xffffffffu, lr1, j0);
                float B1 = __shfl_sync(0xffffffffu, lr1, j1);
                if (hi) { L0 = B0; L1 = B1; }
            }
            float4 F0 = f4[(size_t)s0 * 16 + q];
            float4 F1 = f4[(size_t)s1 * 16 + q];
            float a0 = __expf(L0 - mm) * ii;
            float a1 = __expf(L1 - mm) * ii;
            acc.x += a0 * F0.x + a1 * F1.x;
            acc.y += a0 * F0.y + a1 * F1.y;
            acc.z += a0 * F0.z + a1 * F1.z;
            acc.w += a0 * F0.w + a1 * F1.w;
        }
        for (; e < end; e += 2) {
            int idx = e + sub;
            bool v = idx < end;
            int j = (idx - beg) & 31;
            int ss = g_src[v ? idx : (end - 1)];
            float A = __shfl_sync(0xffffffffu, lr0, j);
            float L = A;
            if (HEADS == 2) {
                float B = __shfl_sync(0xffffffffu, lr1, j);
                if (hi) L = B;
            }
            float4 F = f4[(size_t)ss * 16 + q];
            float a = v ? __expf(L - mm) * ii : 0.f;
            acc.x += a * F.x; acc.y += a * F.y;
            acc.z += a * F.z; acc.w += a * F.w;
        }
    } else {
        for (; e + 4 <= end; e += 4) {
            int s0 = g_src[e + sub], s1 = g_src[e + 2 + sub];
            float2 l0 = g_elog[e + sub], l1 = g_elog[e + 2 + sub];
            float4 F0 = f4[(size_t)s0 * 16 + q];
            float4 F1 = f4[(size_t)s1 * 16 + q];
            float a0 = __expf((hi ? l0.y : l0.x) - mm) * ii;
            float a1 = __expf((hi ? l1.y : l1.x) - mm) * ii;
            acc.x += a0 * F0.x + a1 * F1.x;
            acc.y += a0 * F0.y + a1 * F1.y;
            acc.z += a0 * F0.z + a1 * F1.z;
            acc.w += a0 * F0.w + a1 * F1.w;
        }
        for (; e < end; e += 2) {
            int idx = e + sub;
            bool v = idx < end;
            int ix = v ? idx : (end - 1);
            int ss = g_src[ix];
            float2 l = g_elog[ix];
            float4 F = f4[(size_t)ss * 16 + q];
            float a = v ? __expf((hi ? l.y : l.x) - mm) * ii : 0.f;
            acc.x += a * F.x; acc.y += a * F.y;
            acc.z += a * F.z; acc.w += a * F.w;
        }
    }

    // combine even/odd halves
    acc.x += __shfl_xor_sync(0xffffffffu, acc.x, 16);
    acc.y += __shfl_xor_sync(0xffffffffu, acc.y, 16);
    acc.z += __shfl_xor_sync(0xffffffffu, acc.z, 16);
    acc.w += __shfl_xor_sync(0xffffffffu, acc.w, 16);

    if (lane < 16) {
        float4 bv = ((const float4*)bias)[q];
        float4 r;
        r.x = acc.x + bv.x; r.y = acc.y + bv.y;
        r.z = acc.z + bv.z; r.w = acc.w + bv.w;
        if (RELU) {
            r.x = fmaxf(r.x, 0.f); r.y = fmaxf(r.y, 0.f);
            r.z = fmaxf(r.z, 0.f); r.w = fmaxf(r.w, 0.f);
        }
        float* dst = TOOUT ? outp : g_buf;
        ((float4*)dst)[(size_t)w * 16 + q] = r;
    }
}

// ---------------- launch ----------------
extern "C" void kernel_launch(void* const* d_in, const int* in_sizes, int n_in,
                              void* d_out, int out_size) {
    const float* x   = (const float*)d_in[0];
    const int*   ei  = (const int*)d_in[1];
    const float* W1  = (const float*)d_in[2];
    const float* as1 = (const float*)d_in[3];
    const float* ad1 = (const float*)d_in[4];
    const float* b1  = (const float*)d_in[5];
    const float* W2  = (const float*)d_in[6];
    const float* as2 = (const float*)d_in[7];
    const float* ad2 = (const float*)d_in[8];
    const float* b2  = (const float*)d_in[9];
    const float* W3  = (const float*)d_in[10];
    const float* as3 = (const float*)d_in[11];
    const float* ad3 = (const float*)d_in[12];
    const float* b3  = (const float*)d_in[13];
    float* out = (float*)d_out;

    cudaStream_t sa;
    cudaEvent_t e0, e1;
    cudaStreamCreateWithFlags(&sa, cudaStreamNonBlocking);
    cudaEventCreateWithFlags(&e0, cudaEventDisableTiming);
    cudaEventCreateWithFlags(&e1, cudaEventDisableTiming);

    const int GB = (Nn + 255) / 256;       // GEMM blocks (256-row tiles)
    const int WG = (Nn * 32 + 255) / 256;  // one warp per node

    // fork: CSR build runs concurrently with layer-1 GEMM.
    // Submission order keeps k_gemm<128> 4th so ncu (-s 5 -c 1) profiles it.
    cudaEventRecord(e0, 0);
    cudaStreamWaitEvent(sa, e0, 0);
    k_zero<<<(Nn + 255) / 256, 256, 0, sa>>>();                 // 1
    k_hist<<<(ETOT + 255) / 256, 256, 0, sa>>>(ei);             // 2
    k_scan1<<<NB, 1024, 0, sa>>>();                             // 3
    k_gemm<128, 2, true><<<GB, 256>>>(x, W1, as1, ad1);         // 4 <- profile target
    k_scan2<<<1, 128, 0, sa>>>();                               // 5
    k_scan3<<<NB, 1024, 0, sa>>>();                             // 6
    k_scatter<<<(ETOT + 255) / 256, 256, 0, sa>>>(ei);          // 7
    cudaEventRecord(e1, sa);

    cudaStreamWaitEvent(0, e1, 0);   // join: edge kernel needs CSR
    k_edge<2, true, false><<<WG, 256>>>(b1, nullptr);

    // layer 2: 64 -> 2x32, relu
    k_gemm<64, 2, false><<<GB, 256>>>(nullptr, W2, as2, ad2);
    k_edge<2, true, false><<<WG, 256>>>(b2, nullptr);

    // layer 3: 64 -> 1x64, no relu, write d_out
    k_gemm<64, 1, false><<<GB, 256>>>(nullptr, W3, as3, ad3);
    k_edge<1, false, true><<<WG, 256>>>(b3, out);
}

// round 10
// speedup vs baseline: 1.8674x; 1.0401x over previous
#include <cuda_runtime.h>
#include <cuda_fp16.h>

#define Nn 100000
#define Ee 1600000
#define ETOT 1700000   // Ee + Nn self loops
#define NB 98          // ceil(Nn/1024)

// ---------------- scratch (device globals; no allocation) ----------------
__device__ int     g_count[Nn];
__device__ int     g_rowptr[Nn + 1];
__device__ int     g_wptr[Nn];
__device__ int     g_bsum[NB];
__device__ int     g_boff[NB];
__device__ int     g_src[ETOT];
__device__ __half2 g_feath[Nn * 32];   // transformed features (fp16, gather-only)
__device__ float   g_buf[Nn * 64];     // aggregated output (fp32, ping-pong)
__device__ float2  g_alsrc[Nn];        // per-node attention logits (src side)
__device__ float2  g_aldst[Nn];        // per-node attention logits (dst side)
__device__ float2  g_elog[ETOT];       // spill for nodes with degree > 32

__device__ __forceinline__ float lrelu(float x) { return fmaxf(x, 0.2f * x); }

// ---------------- CSR construction ----------------
__global__ void k_zero() {
    int i = blockIdx.x * blockDim.x + threadIdx.x;
    if (i < Nn) g_count[i] = 0;
}

__global__ void k_hist(const int* __restrict__ ei) {
    int i = blockIdx.x * blockDim.x + threadIdx.x;
    if (i >= ETOT) return;
    int d = (i < Ee) ? ei[Ee + i] : (i - Ee);
    atomicAdd(&g_count[d], 1);
}

__global__ void k_scan1() {
    __shared__ int s[1024];
    int t = threadIdx.x, i = blockIdx.x * 1024 + t;
    int v = (i < Nn) ? g_count[i] : 0;
    s[t] = v;
    __syncthreads();
    for (int o = 1; o < 1024; o <<= 1) {
        int a = (t >= o) ? s[t - o] : 0;
        __syncthreads();
        s[t] += a;
        __syncthreads();
    }
    if (i < Nn) g_rowptr[i + 1] = s[t];
    if (t == 1023) g_bsum[blockIdx.x] = s[t];
}

__global__ void k_scan2() {
    __shared__ int s[128];
    int t = threadIdx.x;
    s[t] = (t < NB) ? g_bsum[t] : 0;
    __syncthreads();
    for (int o = 1; o < 128; o <<= 1) {
        int a = (t >= o) ? s[t - o] : 0;
        __syncthreads();
        s[t] += a;
        __syncthreads();
    }
    if (t < NB) g_boff[t] = (t == 0) ? 0 : s[t - 1];
}

__global__ void k_scan3() {   // also produces g_wptr (= final rowptr)
    int t = threadIdx.x, i = blockIdx.x * 1024 + t;
    if (i < Nn) {
        int v = g_rowptr[i + 1] + g_boff[blockIdx.x];
        g_rowptr[i + 1] = v;
        if (i + 1 < Nn) g_wptr[i + 1] = v;
    }
    if (i == 0) { g_rowptr[0] = 0; g_wptr[0] = 0; }
}

__global__ void k_scatter(const int* __restrict__ ei) {
    int i = blockIdx.x * blockDim.x + threadIdx.x;
    if (i >= ETOT) return;
    int s, d;
    if (i < Ee) { s = ei[i]; d = ei[Ee + i]; }
    else        { s = d = i - Ee; }
    int pos = atomicAdd(&g_wptr[d], 1);
    g_src[pos] = s;
}

// ---------------- GEMM (8x8 register tile) + attention-logit epilogue --------
// Block tile: 128 rows x 64 cols (128 threads -> 3 blocks/SM), K chunked by 32.
// Thread (cx = t&7, ry = t>>3) computes rows ry*8..+7, cols cx*8..+7.
template <int K, int HEADS, bool FROMX>
__global__ void __launch_bounds__(128) k_gemm(const float* __restrict__ Xp,
                                              const float* __restrict__ W,
                                              const float* __restrict__ av,
                                              const float* __restrict__ dv) {
    constexpr int KC  = 32;
    constexpr int STR = KC + 5;            // 37: conflict-free scalar LDS
    __shared__ float sX[128 * STR];        // 18944 B
    __shared__ float sW[KC * 64];          // 8192 B
    const float* X = FROMX ? Xp : g_buf;
    int t = threadIdx.x;
    int row0 = blockIdx.x * 128;
    int cx = t & 7;        // column group: cols cx*8..cx*8+7
    int ry = t >> 3;       // row group (0..15): rows ry*8..ry*8+7

    float acc[8][8];
#pragma unroll
    for (int i = 0; i < 8; i++)
#pragma unroll
        for (int j = 0; j < 8; j++) acc[i][j] = 0.f;

    for (int k0 = 0; k0 < K; k0 += KC) {
        // load X chunk (128 rows x 32 k) : 1024 float4, 8 per thread
#pragma unroll
        for (int i = 0; i < 8; i++) {
            int idx = t + i * 128;
            int r = idx >> 3;
            int k4 = (idx & 7) << 2;
            int grow = row0 + r;
            float4 v = make_float4(0.f, 0.f, 0.f, 0.f);
            if (grow < Nn) v = *(const float4*)&X[(size_t)grow * K + k0 + k4];
            sX[r * STR + k4]     = v.x;
            sX[r * STR + k4 + 1] = v.y;
            sX[r * STR + k4 + 2] = v.z;
            sX[r * STR + k4 + 3] = v.w;
        }
        // load W chunk (32 x 64) : 512 float4, 4 per thread
#pragma unroll
        for (int i = 0; i < 4; i++) {
            int idx = t + i * 128;
            int k = idx >> 4;
            int c4 = (idx & 15) << 2;
            *(float4*)&sW[k * 64 + c4] = *(const float4*)&W[(size_t)(k0 + k) * 64 + c4];
        }
        __syncthreads();

#pragma unroll
        for (int k = 0; k < KC; k++) {
            float xr[8];
#pragma unroll
            for (int i = 0; i < 8; i++) xr[i] = sX[(ry * 8 + i) * STR + k];
            float4 w0 = *(const float4*)&sW[k * 64 + cx * 8];
            float4 w1 = *(const float4*)&sW[k * 64 + cx * 8 + 4];
#pragma unroll
            for (int i = 0; i < 8; i++) {
                acc[i][0] += xr[i] * w0.x;
                acc[i][1] += xr[i] * w0.y;
                acc[i][2] += xr[i] * w0.z;
                acc[i][3] += xr[i] * w0.w;
                acc[i][4] += xr[i] * w1.x;
                acc[i][5] += xr[i] * w1.y;
                acc[i][6] += xr[i] * w1.z;
                acc[i][7] += xr[i] * w1.w;
            }
        }
        __syncthreads();
    }

    // epilogue: store feat (fp16) + per-row attention logits (fp32)
    float4 avA = *(const float4*)&av[cx * 8];
    float4 avB = *(const float4*)&av[cx * 8 + 4];
    float4 dvA = *(const float4*)&dv[cx * 8];
    float4 dvB = *(const float4*)&dv[cx * 8 + 4];

#pragma unroll
    for (int i = 0; i < 8; i++) {
        int grow = row0 + ry * 8 + i;
        bool ok = (grow < Nn);
        if (ok) {
            __half2 h0 = __floats2half2_rn(acc[i][0], acc[i][1]);
            __half2 h1 = __floats2half2_rn(acc[i][2], acc[i][3]);
            __half2 h2 = __floats2half2_rn(acc[i][4], acc[i][5]);
            __half2 h3 = __floats2half2_rn(acc[i][6], acc[i][7]);
            uint4 pack;
            pack.x = *(unsigned*)&h0; pack.y = *(unsigned*)&h1;
            pack.z = *(unsigned*)&h2; pack.w = *(unsigned*)&h3;
            *(uint4*)&g_feath[(size_t)grow * 32 + cx * 4] = pack;
        }
        float ps = acc[i][0] * avA.x + acc[i][1] * avA.y + acc[i][2] * avA.z + acc[i][3] * avA.w
                 + acc[i][4] * avB.x + acc[i][5] * avB.y + acc[i][6] * avB.z + acc[i][7] * avB.w;
        float pd = acc[i][0] * dvA.x + acc[i][1] * dvA.y + acc[i][2] * dvA.z + acc[i][3] * dvA.w
                 + acc[i][4] * dvB.x + acc[i][5] * dvB.y + acc[i][6] * dvB.z + acc[i][7] * dvB.w;
        // reduce within 4-lane subgroup (cx 0-3 = head0 cols, cx 4-7 = head1 cols)
        ps += __shfl_xor_sync(0xffffffffu, ps, 1);
        ps += __shfl_xor_sync(0xffffffffu, ps, 2);
        pd += __shfl_xor_sync(0xffffffffu, pd, 1);
        pd += __shfl_xor_sync(0xffffffffu, pd, 2);
        if (HEADS == 2) {
            float ps1 = __shfl_xor_sync(0xffffffffu, ps, 4);  // other head's sum
            float pd1 = __shfl_xor_sync(0xffffffffu, pd, 4);
            if (cx == 0 && ok) {
                g_alsrc[grow] = make_float2(ps, ps1);
                g_aldst[grow] = make_float2(pd, pd1);
            }
        } else {
            ps += __shfl_xor_sync(0xffffffffu, ps, 4);
            pd += __shfl_xor_sync(0xffffffffu, pd, 4);
            if (cx == 0 && ok) {
                g_alsrc[grow] = make_float2(ps, 0.f);
                g_aldst[grow] = make_float2(pd, 0.f);
            }
        }
    }
}

// ---------------- warp-per-dst: online softmax + weighted gather ----------------
// Pass 1: lane = edge (striped). Pass 2: half-warp per edge, lane = 4 fp16
// channels (8B). Lanes 0-15 even edges, 16-31 odd edges; shfl_xor(16) combine.
template <int HEADS, bool RELU, bool TOOUT>
__global__ void __launch_bounds__(256) k_edge(const float* __restrict__ bias,
                                              float* __restrict__ outp) {
    int w = (blockIdx.x * blockDim.x + threadIdx.x) >> 5;
    int lane = threadIdx.x & 31;
    if (w >= Nn) return;
    int beg = g_rowptr[w], end = g_rowptr[w + 1];
    int deg = end - beg;
    bool small = (deg <= 32);

    float2 ad = g_aldst[w];

    // ---- pass 1: online softmax (max + denom in one sweep) ----
    float m0 = -1e30f, m1 = -1e30f, d0 = 0.f, d1 = 0.f;
    float lr0 = -1e30f, lr1 = -1e30f;  // this lane's edge logits (small path)
    for (int e = beg + lane; e < end; e += 32) {
        int s = g_src[e];
        float2 as = g_alsrc[s];
        float l0 = lrelu(as.x + ad.x);
        float l1 = (HEADS == 2) ? lrelu(as.y + ad.y) : 0.f;
        if (small) { lr0 = l0; lr1 = l1; }
        else       g_elog[e] = make_float2(l0, l1);
        float nm0 = fmaxf(m0, l0);
        d0 = d0 * __expf(m0 - nm0) + __expf(l0 - nm0);
        m0 = nm0;
        if (HEADS == 2) {
            float nm1 = fmaxf(m1, l1);
            d1 = d1 * __expf(m1 - nm1) + __expf(l1 - nm1);
            m1 = nm1;
        }
    }
    float M0 = m0, M1 = m1;
#pragma unroll
    for (int o = 16; o; o >>= 1) {
        M0 = fmaxf(M0, __shfl_xor_sync(0xffffffffu, M0, o));
        if (HEADS == 2) M1 = fmaxf(M1, __shfl_xor_sync(0xffffffffu, M1, o));
    }
    d0 *= __expf(m0 - M0);
    if (HEADS == 2) d1 *= __expf(m1 - M1);
#pragma unroll
    for (int o = 16; o; o >>= 1) {
        d0 += __shfl_xor_sync(0xffffffffu, d0, o);
        if (HEADS == 2) d1 += __shfl_xor_sync(0xffffffffu, d1, o);
    }
    float inv0 = 1.f / d0;
    float inv1 = (HEADS == 2) ? 1.f / d1 : 0.f;
    __syncwarp();

    // ---- pass 2: half-warp per edge, 4 fp16 channels per lane ----
    int sub = lane >> 4;     // 0 = even edges, 1 = odd edges
    int q   = lane & 15;     // channel group: channels 4q..4q+3
    bool hi = (HEADS == 2) && (q >= 8);   // channels >= 32 -> head 1
    float mm = hi ? M1 : M0;
    float ii = hi ? inv1 : inv0;

    const uint2* fh = (const uint2*)g_feath;   // uint2 = 4 halves
    float4 acc = make_float4(0.f, 0.f, 0.f, 0.f);
    int e = beg;
    if (small) {
        for (; e + 4 <= end; e += 4) {
            int j0 = e - beg + sub, j1 = j0 + 2;
            int s0 = g_src[e + sub], s1 = g_src[e + 2 + sub];
            float A0 = __shfl_sync(0xffffffffu, lr0, j0);
            float A1 = __shfl_sync(0xffffffffu, lr0, j1);
            float L0 = A0, L1 = A1;
            if (HEADS == 2) {
                float B0 = __shfl_sync(0xffffffffu, lr1, j0);
                float B1 = __shfl_sync(0xffffffffu, lr1, j1);
                if (hi) { L0 = B0; L1 = B1; }
            }
            uint2 u0 = fh[(size_t)s0 * 16 + q];
            uint2 u1 = fh[(size_t)s1 * 16 + q];
            float2 p0 = __half22float2(*(__half2*)&u0.x);
            float2 p1 = __half22float2(*(__half2*)&u0.y);
            float2 p2 = __half22float2(*(__half2*)&u1.x);
            float2 p3 = __half22float2(*(__half2*)&u1.y);
            float a0 = __expf(L0 - mm) * ii;
            float a1 = __expf(L1 - mm) * ii;
            acc.x += a0 * p0.x + a1 * p2.x;
            acc.y += a0 * p0.y + a1 * p2.y;
            acc.z += a0 * p1.x + a1 * p3.x;
            acc.w += a0 * p1.y + a1 * p3.y;
        }
        for (; e < end; e += 2) {
            int idx = e + sub;
            bool v = idx < end;
            int j = (idx - beg) & 31;
            int ss = g_src[v ? idx : (end - 1)];
            float A = __shfl_sync(0xffffffffu, lr0, j);
            float L = A;
            if (HEADS == 2) {
                float B = __shfl_sync(0xffffffffu, lr1, j);
                if (hi) L = B;
            }
            uint2 u = fh[(size_t)ss * 16 + q];
            float2 p0 = __half22float2(*(__half2*)&u.x);
            float2 p1 = __half22float2(*(__half2*)&u.y);
            float a = v ? __expf(L - mm) * ii : 0.f;
            acc.x += a * p0.x; acc.y += a * p0.y;
            acc.z += a * p1.x; acc.w += a * p1.y;
        }
    } else {
        for (; e + 4 <= end; e += 4) {
            int s0 = g_src[e + sub], s1 = g_src[e + 2 + sub];
            float2 l0 = g_elog[e + sub], l1 = g_elog[e + 2 + sub];
            uint2 u0 = fh[(size_t)s0 * 16 + q];
            uint2 u1 = fh[(size_t)s1 * 16 + q];
            float2 p0 = __half22float2(*(__half2*)&u0.x);
            float2 p1 = __half22float2(*(__half2*)&u0.y);
            float2 p2 = __half22float2(*(__half2*)&u1.x);
            float2 p3 = __half22float2(*(__half2*)&u1.y);
            float a0 = __expf((hi ? l0.y : l0.x) - mm) * ii;
            float a1 = __expf((hi ? l1.y : l1.x) - mm) * ii;
            acc.x += a0 * p0.x + a1 * p2.x;
            acc.y += a0 * p0.y + a1 * p2.y;
            acc.z += a0 * p1.x + a1 * p3.x;
            acc.w += a0 * p1.y + a1 * p3.y;
        }
        for (; e < end; e += 2) {
            int idx = e + sub;
            bool v = idx < end;
            int ix = v ? idx : (end - 1);
            int ss = g_src[ix];
            float2 l = g_elog[ix];
            uint2 u = fh[(size_t)ss * 16 + q];
            float2 p0 = __half22float2(*(__half2*)&u.x);
            float2 p1 = __half22float2(*(__half2*)&u.y);
            float a = v ? __expf((hi ? l.y : l.x) - mm) * ii : 0.f;
            acc.x += a * p0.x; acc.y += a * p0.y;
            acc.z += a * p1.x; acc.w += a * p1.y;
        }
    }

    // combine even/odd halves
    acc.x += __shfl_xor_sync(0xffffffffu, acc.x, 16);
    acc.y += __shfl_xor_sync(0xffffffffu, acc.y, 16);
    acc.z += __shfl_xor_sync(0xffffffffu, acc.z, 16);
    acc.w += __shfl_xor_sync(0xffffffffu, acc.w, 16);

    if (lane < 16) {
        float4 bv = ((const float4*)bias)[q];
        float4 r;
        r.x = acc.x + bv.x; r.y = acc.y + bv.y;
        r.z = acc.z + bv.z; r.w = acc.w + bv.w;
        if (RELU) {
            r.x = fmaxf(r.x, 0.f); r.y = fmaxf(r.y, 0.f);
            r.z = fmaxf(r.z, 0.f); r.w = fmaxf(r.w, 0.f);
        }
        float* dst = TOOUT ? outp : g_buf;
        ((float4*)dst)[(size_t)w * 16 + q] = r;
    }
}

// ---------------- launch ----------------
extern "C" void kernel_launch(void* const* d_in, const int* in_sizes, int n_in,
                              void* d_out, int out_size) {
    const float* x   = (const float*)d_in[0];
    const int*   ei  = (const int*)d_in[1];
    const float* W1  = (const float*)d_in[2];
    const float* as1 = (const float*)d_in[3];
    const float* ad1 = (const float*)d_in[4];
    const float* b1  = (const float*)d_in[5];
    const float* W2  = (const float*)d_in[6];
    const float* as2 = (const float*)d_in[7];
    const float* ad2 = (const float*)d_in[8];
    const float* b2  = (const float*)d_in[9];
    const float* W3  = (const float*)d_in[10];
    const float* as3 = (const float*)d_in[11];
    const float* ad3 = (const float*)d_in[12];
    const float* b3  = (const float*)d_in[13];
    float* out = (float*)d_out;

    cudaStream_t sa;
    cudaEvent_t e0, e1;
    cudaStreamCreateWithFlags(&sa, cudaStreamNonBlocking);
    cudaEventCreateWithFlags(&e0, cudaEventDisableTiming);
    cudaEventCreateWithFlags(&e1, cudaEventDisableTiming);

    const int GB = (Nn + 127) / 128;       // GEMM blocks (128-row tiles)
    const int WG = (Nn * 32 + 255) / 256;  // one warp per node

    // fork: CSR build runs concurrently with layer-1 GEMM.
    // Submission order keeps k_gemm<128> 4th so ncu (-s 5 -c 1) profiles it.
    cudaEventRecord(e0, 0);
    cudaStreamWaitEvent(sa, e0, 0);
    k_zero<<<(Nn + 255) / 256, 256, 0, sa>>>();                 // 1
    k_hist<<<(ETOT + 255) / 256, 256, 0, sa>>>(ei);             // 2
    k_scan1<<<NB, 1024, 0, sa>>>();                             // 3
    k_gemm<128, 2, true><<<GB, 128>>>(x, W1, as1, ad1);         // 4 <- profile target
    k_scan2<<<1, 128, 0, sa>>>();                               // 5
    k_scan3<<<NB, 1024, 0, sa>>>();                             // 6
    k_scatter<<<(ETOT + 255) / 256, 256, 0, sa>>>(ei);          // 7
    cudaEventRecord(e1, sa);

    cudaStreamWaitEvent(0, e1, 0);   // join: edge kernel needs CSR
    k_edge<2, true, false><<<WG, 256>>>(b1, nullptr);

    // layer 2: 64 -> 2x32, relu
    k_gemm<64, 2, false><<<GB, 128>>>(nullptr, W2, as2, ad2);
    k_edge<2, true, false><<<WG, 256>>>(b2, nullptr);

    // layer 3: 64 -> 1x64, no relu, write d_out
    k_gemm<64, 1, false><<<GB, 128>>>(nullptr, W3, as3, ad3);
    k_edge<1, false, true><<<WG, 256>>>(b3, out);
}

// round 11
// speedup vs baseline: 1.9823x; 1.0616x over previous
#include <cuda_runtime.h>
#include <cuda_fp16.h>

#define Nn 100000
#define Ee 1600000
#define ETOT 1700000   // Ee + Nn self loops
#define NB 98          // ceil(Nn/1024)

// ---------------- scratch (device globals; no allocation) ----------------
__device__ int     g_count[Nn];
__device__ int     g_rowptr[Nn + 1];
__device__ int     g_wptr[Nn];
__device__ int     g_bsum[NB];
__device__ int     g_boff[NB];
__device__ int     g_src[ETOT];
__device__ __half2 g_feath[Nn * 32];   // transformed features (fp16, gather-only)
__device__ float   g_buf[Nn * 64];     // aggregated output (fp32, ping-pong)
__device__ float2  g_alsrc[Nn];        // per-node attention logits (src side)
__device__ float2  g_aldst[Nn];        // per-node attention logits (dst side)

__device__ __forceinline__ float lrelu(float x) { return fmaxf(x, 0.2f * x); }

// ---------------- CSR construction ----------------
__global__ void k_zero() {
    int i = blockIdx.x * blockDim.x + threadIdx.x;
    if (i < Nn) g_count[i] = 0;
}

__global__ void k_hist(const int* __restrict__ ei) {
    int i = blockIdx.x * blockDim.x + threadIdx.x;
    if (i >= ETOT) return;
    int d = (i < Ee) ? ei[Ee + i] : (i - Ee);
    atomicAdd(&g_count[d], 1);
}

__global__ void k_scan1() {
    __shared__ int s[1024];
    int t = threadIdx.x, i = blockIdx.x * 1024 + t;
    int v = (i < Nn) ? g_count[i] : 0;
    s[t] = v;
    __syncthreads();
    for (int o = 1; o < 1024; o <<= 1) {
        int a = (t >= o) ? s[t - o] : 0;
        __syncthreads();
        s[t] += a;
        __syncthreads();
    }
    if (i < Nn) g_rowptr[i + 1] = s[t];
    if (t == 1023) g_bsum[blockIdx.x] = s[t];
}

__global__ void k_scan2() {
    __shared__ int s[128];
    int t = threadIdx.x;
    s[t] = (t < NB) ? g_bsum[t] : 0;
    __syncthreads();
    for (int o = 1; o < 128; o <<= 1) {
        int a = (t >= o) ? s[t - o] : 0;
        __syncthreads();
        s[t] += a;
        __syncthreads();
    }
    if (t < NB) g_boff[t] = (t == 0) ? 0 : s[t - 1];
}

__global__ void k_scan3() {   // also produces g_wptr (= final rowptr)
    int t = threadIdx.x, i = blockIdx.x * 1024 + t;
    if (i < Nn) {
        int v = g_rowptr[i + 1] + g_boff[blockIdx.x];
        g_rowptr[i + 1] = v;
        if (i + 1 < Nn) g_wptr[i + 1] = v;
    }
    if (i == 0) { g_rowptr[0] = 0; g_wptr[0] = 0; }
}

__global__ void k_scatter(const int* __restrict__ ei) {
    int i = blockIdx.x * blockDim.x + threadIdx.x;
    if (i >= ETOT) return;
    int s, d;
    if (i < Ee) { s = ei[i]; d = ei[Ee + i]; }
    else        { s = d = i - Ee; }
    int pos = atomicAdd(&g_wptr[d], 1);
    g_src[pos] = s;
}

// ---------------- GEMM (8x8 register tile) + attention-logit epilogue --------
template <int K, int HEADS, bool FROMX>
__global__ void __launch_bounds__(128) k_gemm(const float* __restrict__ Xp,
                                              const float* __restrict__ W,
                                              const float* __restrict__ av,
                                              const float* __restrict__ dv) {
    constexpr int KC  = 32;
    constexpr int STR = KC + 5;            // 37: conflict-free scalar LDS
    __shared__ float sX[128 * STR];        // 18944 B
    __shared__ float sW[KC * 64];          // 8192 B
    const float* X = FROMX ? Xp : g_buf;
    int t = threadIdx.x;
    int row0 = blockIdx.x * 128;
    int cx = t & 7;        // column group: cols cx*8..cx*8+7
    int ry = t >> 3;       // row group (0..15): rows ry*8..ry*8+7

    float acc[8][8];
#pragma unroll
    for (int i = 0; i < 8; i++)
#pragma unroll
        for (int j = 0; j < 8; j++) acc[i][j] = 0.f;

    for (int k0 = 0; k0 < K; k0 += KC) {
#pragma unroll
        for (int i = 0; i < 8; i++) {
            int idx = t + i * 128;
            int r = idx >> 3;
            int k4 = (idx & 7) << 2;
            int grow = row0 + r;
            float4 v = make_float4(0.f, 0.f, 0.f, 0.f);
            if (grow < Nn) v = *(const float4*)&X[(size_t)grow * K + k0 + k4];
            sX[r * STR + k4]     = v.x;
            sX[r * STR + k4 + 1] = v.y;
            sX[r * STR + k4 + 2] = v.z;
            sX[r * STR + k4 + 3] = v.w;
        }
#pragma unroll
        for (int i = 0; i < 4; i++) {
            int idx = t + i * 128;
            int k = idx >> 4;
            int c4 = (idx & 15) << 2;
            *(float4*)&sW[k * 64 + c4] = *(const float4*)&W[(size_t)(k0 + k) * 64 + c4];
        }
        __syncthreads();

#pragma unroll
        for (int k = 0; k < KC; k++) {
            float xr[8];
#pragma unroll
            for (int i = 0; i < 8; i++) xr[i] = sX[(ry * 8 + i) * STR + k];
            float4 w0 = *(const float4*)&sW[k * 64 + cx * 8];
            float4 w1 = *(const float4*)&sW[k * 64 + cx * 8 + 4];
#pragma unroll
            for (int i = 0; i < 8; i++) {
                acc[i][0] += xr[i] * w0.x;
                acc[i][1] += xr[i] * w0.y;
                acc[i][2] += xr[i] * w0.z;
                acc[i][3] += xr[i] * w0.w;
                acc[i][4] += xr[i] * w1.x;
                acc[i][5] += xr[i] * w1.y;
                acc[i][6] += xr[i] * w1.z;
                acc[i][7] += xr[i] * w1.w;
            }
        }
        __syncthreads();
    }

    // epilogue: store feat (fp16) + per-row attention logits (fp32)
    float4 avA = *(const float4*)&av[cx * 8];
    float4 avB = *(const float4*)&av[cx * 8 + 4];
    float4 dvA = *(const float4*)&dv[cx * 8];
    float4 dvB = *(const float4*)&dv[cx * 8 + 4];

#pragma unroll
    for (int i = 0; i < 8; i++) {
        int grow = row0 + ry * 8 + i;
        bool ok = (grow < Nn);
        if (ok) {
            __half2 h0 = __floats2half2_rn(acc[i][0], acc[i][1]);
            __half2 h1 = __floats2half2_rn(acc[i][2], acc[i][3]);
            __half2 h2 = __floats2half2_rn(acc[i][4], acc[i][5]);
            __half2 h3 = __floats2half2_rn(acc[i][6], acc[i][7]);
            uint4 pack;
            pack.x = *(unsigned*)&h0; pack.y = *(unsigned*)&h1;
            pack.z = *(unsigned*)&h2; pack.w = *(unsigned*)&h3;
            *(uint4*)&g_feath[(size_t)grow * 32 + cx * 4] = pack;
        }
        float ps = acc[i][0] * avA.x + acc[i][1] * avA.y + acc[i][2] * avA.z + acc[i][3] * avA.w
                 + acc[i][4] * avB.x + acc[i][5] * avB.y + acc[i][6] * avB.z + acc[i][7] * avB.w;
        float pd = acc[i][0] * dvA.x + acc[i][1] * dvA.y + acc[i][2] * dvA.z + acc[i][3] * dvA.w
                 + acc[i][4] * dvB.x + acc[i][5] * dvB.y + acc[i][6] * dvB.z + acc[i][7] * dvB.w;
        ps += __shfl_xor_sync(0xffffffffu, ps, 1);
        ps += __shfl_xor_sync(0xffffffffu, ps, 2);
        pd += __shfl_xor_sync(0xffffffffu, pd, 1);
        pd += __shfl_xor_sync(0xffffffffu, pd, 2);
        if (HEADS == 2) {
            float ps1 = __shfl_xor_sync(0xffffffffu, ps, 4);
            float pd1 = __shfl_xor_sync(0xffffffffu, pd, 4);
            if (cx == 0 && ok) {
                g_alsrc[grow] = make_float2(ps, ps1);
                g_aldst[grow] = make_float2(pd, pd1);
            }
        } else {
            ps += __shfl_xor_sync(0xffffffffu, ps, 4);
            pd += __shfl_xor_sync(0xffffffffu, pd, 4);
            if (cx == 0 && ok) {
                g_alsrc[grow] = make_float2(ps, 0.f);
                g_aldst[grow] = make_float2(pd, 0.f);
            }
        }
    }
}

// ---------------- warp-per-dst: SINGLE-PASS flash-style softmax-aggregate ----
// Half-warp sub owns edges beg+sub, beg+sub+2, ...; lane q owns 4 fp16 channels.
// Each lane keeps running (max m, denom d, acc[4]) with online rescaling; the
// two halves merge at the end via shfl_xor(16) + one rescale.
template <int HEADS, bool RELU, bool TOOUT>
__global__ void __launch_bounds__(256) k_edge(const float* __restrict__ bias,
                                              float* __restrict__ outp) {
    int w = (blockIdx.x * blockDim.x + threadIdx.x) >> 5;
    int lane = threadIdx.x & 31;
    if (w >= Nn) return;
    int beg = g_rowptr[w], end = g_rowptr[w + 1];

    int sub = lane >> 4;                  // 0 = even edges, 1 = odd edges
    int q   = lane & 15;                  // channel group: channels 4q..4q+3
    bool hi = (HEADS == 2) && (q >= 8);   // channels >= 32 -> head 1
    float2 ad2 = g_aldst[w];
    float adh = hi ? ad2.y : ad2.x;

    const uint2* fh = (const uint2*)g_feath;   // uint2 = 4 halves
    float m = -1e30f, d = 0.f;
    float ax = 0.f, ay = 0.f, az = 0.f, aw = 0.f;

    int e = beg + sub;
    // 2 edges per iteration (independent loads -> MLP)
    for (; e + 2 < end; e += 4) {
        int s0 = g_src[e], s1 = g_src[e + 2];
        float2 as0 = g_alsrc[s0];
        float2 as1 = g_alsrc[s1];
        uint2 u0 = fh[(size_t)s0 * 16 + q];
        uint2 u1 = fh[(size_t)s1 * 16 + q];
        float l0 = lrelu((hi ? as0.y : as0.x) + adh);
        float l1 = lrelu((hi ? as1.y : as1.x) + adh);
        float nm = fmaxf(m, fmaxf(l0, l1));
        float c  = __expf(m - nm);
        float p0 = __expf(l0 - nm);
        float p1 = __expf(l1 - nm);
        float2 f0 = __half22float2(*(__half2*)&u0.x);
        float2 f1 = __half22float2(*(__half2*)&u0.y);
        float2 f2 = __half22float2(*(__half2*)&u1.x);
        float2 f3 = __half22float2(*(__half2*)&u1.y);
        ax = ax * c + p0 * f0.x + p1 * f2.x;
        ay = ay * c + p0 * f0.y + p1 * f2.y;
        az = az * c + p0 * f1.x + p1 * f3.x;
        aw = aw * c + p0 * f1.y + p1 * f3.y;
        d  = d  * c + p0 + p1;
        m = nm;
    }
    if (e < end) {   // at most one remaining edge for this half
        int s0 = g_src[e];
        float2 as0 = g_alsrc[s0];
        uint2 u0 = fh[(size_t)s0 * 16 + q];
        float l0 = lrelu((hi ? as0.y : as0.x) + adh);
        float nm = fmaxf(m, l0);
        float c  = __expf(m - nm);
        float p0 = __expf(l0 - nm);
        float2 f0 = __half22float2(*(__half2*)&u0.x);
        float2 f1 = __half22float2(*(__half2*)&u0.y);
        ax = ax * c + p0 * f0.x;
        ay = ay * c + p0 * f0.y;
        az = az * c + p0 * f1.x;
        aw = aw * c + p0 * f1.y;
        d  = d  * c + p0;
        m = nm;
    }

    // merge the two halves (lanes with same q, different sub)
    float mo = __shfl_xor_sync(0xffffffffu, m, 16);
    float M  = fmaxf(m, mo);
    float cs = __expf(m - M);       // 0 if this half was empty (m = -1e30)
    ax *= cs; ay *= cs; az *= cs; aw *= cs; d *= cs;
    ax += __shfl_xor_sync(0xffffffffu, ax, 16);
    ay += __shfl_xor_sync(0xffffffffu, ay, 16);
    az += __shfl_xor_sync(0xffffffffu, az, 16);
    aw += __shfl_xor_sync(0xffffffffu, aw, 16);
    d  += __shfl_xor_sync(0xffffffffu, d, 16);
    float inv = 1.f / d;

    if (lane < 16) {
        float4 bv = ((const float4*)bias)[q];
        float4 r;
        r.x = ax * inv + bv.x; r.y = ay * inv + bv.y;
        r.z = az * inv + bv.z; r.w = aw * inv + bv.w;
        if (RELU) {
            r.x = fmaxf(r.x, 0.f); r.y = fmaxf(r.y, 0.f);
            r.z = fmaxf(r.z, 0.f); r.w = fmaxf(r.w, 0.f);
        }
        float* dst = TOOUT ? outp : g_buf;
        ((float4*)dst)[(size_t)w * 16 + q] = r;
    }
}

// ---------------- launch ----------------
extern "C" void kernel_launch(void* const* d_in, const int* in_sizes, int n_in,
                              void* d_out, int out_size) {
    const float* x   = (const float*)d_in[0];
    const int*   ei  = (const int*)d_in[1];
    const float* W1  = (const float*)d_in[2];
    const float* as1 = (const float*)d_in[3];
    const float* ad1 = (const float*)d_in[4];
    const float* b1  = (const float*)d_in[5];
    const float* W2  = (const float*)d_in[6];
    const float* as2 = (const float*)d_in[7];
    const float* ad2 = (const float*)d_in[8];
    const float* b2  = (const float*)d_in[9];
    const float* W3  = (const float*)d_in[10];
    const float* as3 = (const float*)d_in[11];
    const float* ad3 = (const float*)d_in[12];
    const float* b3  = (const float*)d_in[13];
    float* out = (float*)d_out;

    cudaStream_t sa;
    cudaEvent_t e0, e1;
    cudaStreamCreateWithFlags(&sa, cudaStreamNonBlocking);
    cudaEventCreateWithFlags(&e0, cudaEventDisableTiming);
    cudaEventCreateWithFlags(&e1, cudaEventDisableTiming);

    const int GB = (Nn + 127) / 128;       // GEMM blocks (128-row tiles)
    const int WG = (Nn * 32 + 255) / 256;  // one warp per node

    // fork: CSR build runs concurrently with layer-1 GEMM.
    cudaEventRecord(e0, 0);
    cudaStreamWaitEvent(sa, e0, 0);
    k_zero<<<(Nn + 255) / 256, 256, 0, sa>>>();                 // 1
    k_hist<<<(ETOT + 255) / 256, 256, 0, sa>>>(ei);             // 2
    k_scan1<<<NB, 1024, 0, sa>>>();                             // 3
    k_gemm<128, 2, true><<<GB, 128>>>(x, W1, as1, ad1);         // 4 <- profile target
    k_scan2<<<1, 128, 0, sa>>>();                               // 5
    k_scan3<<<NB, 1024, 0, sa>>>();                             // 6
    k_scatter<<<(ETOT + 255) / 256, 256, 0, sa>>>(ei);          // 7
    cudaEventRecord(e1, sa);

    cudaStreamWaitEvent(0, e1, 0);   // join: edge kernel needs CSR
    k_edge<2, true, false><<<WG, 256>>>(b1, nullptr);

    // layer 2: 64 -> 2x32, relu
    k_gemm<64, 2, false><<<GB, 128>>>(nullptr, W2, as2, ad2);
    k_edge<2, true, false><<<WG, 256>>>(b2, nullptr);

    // layer 3: 64 -> 1x64, no relu, write d_out
    k_gemm<64, 1, false><<<GB, 128>>>(nullptr, W3, as3, ad3);
    k_edge<1, false, true><<<WG, 256>>>(b3, out);
}

// round 12
// speedup vs baseline: 2.0973x; 1.0580x over previous
#include <cuda_runtime.h>
#include <cuda_fp16.h>

#define Nn 100000
#define Ee 1600000
#define ETOT 1700000   // Ee + Nn self loops
#define NB 98          // ceil(Nn/1024)

// ---------------- scratch (device globals; no allocation) ----------------
__device__ int     g_count[Nn];
__device__ int     g_rowptr[Nn + 1];
__device__ int     g_wptr[Nn];
__device__ int     g_bsum[NB];
__device__ int     g_boff[NB];
__device__ int     g_src[ETOT];
__device__ __half2 g_feath[Nn * 32];   // transformed features (fp16, gather-only)
__device__ float   g_buf[Nn * 64];     // aggregated output (fp32, ping-pong)
__device__ float2  g_alsrc[Nn];        // per-node attention logits (src side)
__device__ float2  g_aldst[Nn];        // per-node attention logits (dst side)

__device__ __forceinline__ float lrelu(float x) { return fmaxf(x, 0.2f * x); }

// packed fp32x2 FMA (Blackwell; ptxas never emits it from C++)
__device__ __forceinline__ void ffma2(unsigned long long& d,
                                      unsigned long long a,
                                      unsigned long long b) {
    asm("fma.rn.f32x2 %0, %1, %2, %0;" : "+l"(d) : "l"(a), "l"(b));
}

// ---------------- CSR construction ----------------
__global__ void k_zero() {
    int i = blockIdx.x * blockDim.x + threadIdx.x;
    if (i < Nn) g_count[i] = 0;
}

__global__ void k_hist(const int* __restrict__ ei) {
    int i = blockIdx.x * blockDim.x + threadIdx.x;
    if (i >= ETOT) return;
    int d = (i < Ee) ? ei[Ee + i] : (i - Ee);
    atomicAdd(&g_count[d], 1);
}

__global__ void k_scan1() {
    __shared__ int s[1024];
    int t = threadIdx.x, i = blockIdx.x * 1024 + t;
    int v = (i < Nn) ? g_count[i] : 0;
    s[t] = v;
    __syncthreads();
    for (int o = 1; o < 1024; o <<= 1) {
        int a = (t >= o) ? s[t - o] : 0;
        __syncthreads();
        s[t] += a;
        __syncthreads();
    }
    if (i < Nn) g_rowptr[i + 1] = s[t];
    if (t == 1023) g_bsum[blockIdx.x] = s[t];
}

__global__ void k_scan2() {
    __shared__ int s[128];
    int t = threadIdx.x;
    s[t] = (t < NB) ? g_bsum[t] : 0;
    __syncthreads();
    for (int o = 1; o < 128; o <<= 1) {
        int a = (t >= o) ? s[t - o] : 0;
        __syncthreads();
        s[t] += a;
        __syncthreads();
    }
    if (t < NB) g_boff[t] = (t == 0) ? 0 : s[t - 1];
}

__global__ void k_scan3() {   // also produces g_wptr (= final rowptr)
    int t = threadIdx.x, i = blockIdx.x * 1024 + t;
    if (i < Nn) {
        int v = g_rowptr[i + 1] + g_boff[blockIdx.x];
        g_rowptr[i + 1] = v;
        if (i + 1 < Nn) g_wptr[i + 1] = v;
    }
    if (i == 0) { g_rowptr[0] = 0; g_wptr[0] = 0; }
}

__global__ void k_scatter(const int* __restrict__ ei) {
    int i = blockIdx.x * blockDim.x + threadIdx.x;
    if (i >= ETOT) return;
    int s, d;
    if (i < Ee) { s = ei[i]; d = ei[Ee + i]; }
    else        { s = d = i - Ee; }
    int pos = atomicAdd(&g_wptr[d], 1);
    g_src[pos] = s;
}

// ---------------- GEMM (8x8 tile, f32x2 packed FMA) + logit epilogue --------
// Thread (cx = t&7, ry = t>>3): rows ry*8..+7, cols cx*8..+7. Accumulators are
// 32 packed u64 (col pairs). W pairs load contiguously from sW; x duplicated
// into both lanes via one mov.b64 per row per k.
template <int K, int HEADS, bool FROMX>
__global__ void __launch_bounds__(128) k_gemm(const float* __restrict__ Xp,
                                              const float* __restrict__ W,
                                              const float* __restrict__ av,
                                              const float* __restrict__ dv) {
    constexpr int KC  = 32;
    constexpr int STR = KC + 5;            // 37: conflict-free scalar LDS
    __shared__ float sX[128 * STR];        // 18944 B
    __shared__ float sW[KC * 64];          // 8192 B
    const float* X = FROMX ? Xp : g_buf;
    int t = threadIdx.x;
    int row0 = blockIdx.x * 128;
    int cx = t & 7;
    int ry = t >> 3;

    unsigned long long acc2[8][4];         // 8 rows x 4 col-pairs
#pragma unroll
    for (int i = 0; i < 8; i++)
#pragma unroll
        for (int j = 0; j < 4; j++) acc2[i][j] = 0ull;

    for (int k0 = 0; k0 < K; k0 += KC) {
#pragma unroll
        for (int i = 0; i < 8; i++) {
            int idx = t + i * 128;
            int r = idx >> 3;
            int k4 = (idx & 7) << 2;
            int grow = row0 + r;
            float4 v = make_float4(0.f, 0.f, 0.f, 0.f);
            if (grow < Nn) v = *(const float4*)&X[(size_t)grow * K + k0 + k4];
            sX[r * STR + k4]     = v.x;
            sX[r * STR + k4 + 1] = v.y;
            sX[r * STR + k4 + 2] = v.z;
            sX[r * STR + k4 + 3] = v.w;
        }
#pragma unroll
        for (int i = 0; i < 4; i++) {
            int idx = t + i * 128;
            int k = idx >> 4;
            int c4 = (idx & 15) << 2;
            *(float4*)&sW[k * 64 + c4] = *(const float4*)&W[(size_t)(k0 + k) * 64 + c4];
        }
        __syncthreads();

#pragma unroll
        for (int k = 0; k < KC; k++) {
            ulonglong2 wA = *(const ulonglong2*)&sW[k * 64 + cx * 8];      // cols 0-3
            ulonglong2 wB = *(const ulonglong2*)&sW[k * 64 + cx * 8 + 4];  // cols 4-7
#pragma unroll
            for (int i = 0; i < 8; i++) {
                unsigned xu = __float_as_uint(sX[(ry * 8 + i) * STR + k]);
                unsigned long long xp;
                asm("mov.b64 %0, {%1, %1};" : "=l"(xp) : "r"(xu));
                ffma2(acc2[i][0], xp, wA.x);
                ffma2(acc2[i][1], xp, wA.y);
                ffma2(acc2[i][2], xp, wB.x);
                ffma2(acc2[i][3], xp, wB.y);
            }
        }
        __syncthreads();
    }

    // epilogue: unpack, store feat (fp16) + per-row attention logits (fp32)
    float4 avA = *(const float4*)&av[cx * 8];
    float4 avB = *(const float4*)&av[cx * 8 + 4];
    float4 dvA = *(const float4*)&dv[cx * 8];
    float4 dvB = *(const float4*)&dv[cx * 8 + 4];

#pragma unroll
    for (int i = 0; i < 8; i++) {
        float a[8];
#pragma unroll
        for (int jp = 0; jp < 4; jp++) {
            unsigned lo, hi;
            asm("mov.b64 {%0, %1}, %2;" : "=r"(lo), "=r"(hi) : "l"(acc2[i][jp]));
            a[2 * jp]     = __uint_as_float(lo);
            a[2 * jp + 1] = __uint_as_float(hi);
        }
        int grow = row0 + ry * 8 + i;
        bool ok = (grow < Nn);
        if (ok) {
            __half2 h0 = __floats2half2_rn(a[0], a[1]);
            __half2 h1 = __floats2half2_rn(a[2], a[3]);
            __half2 h2 = __floats2half2_rn(a[4], a[5]);
            __half2 h3 = __floats2half2_rn(a[6], a[7]);
            uint4 pack;
            pack.x = *(unsigned*)&h0; pack.y = *(unsigned*)&h1;
            pack.z = *(unsigned*)&h2; pack.w = *(unsigned*)&h3;
            *(uint4*)&g_feath[(size_t)grow * 32 + cx * 4] = pack;
        }
        float ps = a[0] * avA.x + a[1] * avA.y + a[2] * avA.z + a[3] * avA.w
                 + a[4] * avB.x + a[5] * avB.y + a[6] * avB.z + a[7] * avB.w;
        float pd = a[0] * dvA.x + a[1] * dvA.y + a[2] * dvA.z + a[3] * dvA.w
                 + a[4] * dvB.x + a[5] * dvB.y + a[6] * dvB.z + a[7] * dvB.w;
        ps += __shfl_xor_sync(0xffffffffu, ps, 1);
        ps += __shfl_xor_sync(0xffffffffu, ps, 2);
        pd += __shfl_xor_sync(0xffffffffu, pd, 1);
        pd += __shfl_xor_sync(0xffffffffu, pd, 2);
        if (HEADS == 2) {
            float ps1 = __shfl_xor_sync(0xffffffffu, ps, 4);
            float pd1 = __shfl_xor_sync(0xffffffffu, pd, 4);
            if (cx == 0 && ok) {
                g_alsrc[grow] = make_float2(ps, ps1);
                g_aldst[grow] = make_float2(pd, pd1);
            }
        } else {
            ps += __shfl_xor_sync(0xffffffffu, ps, 4);
            pd += __shfl_xor_sync(0xffffffffu, pd, 4);
            if (cx == 0 && ok) {
                g_alsrc[grow] = make_float2(ps, 0.f);
                g_aldst[grow] = make_float2(pd, 0.f);
            }
        }
    }
}

// ---------------- warp-per-dst: single-pass flash softmax, 4 subgroups ------
// Subgroup sub = lane>>3 owns edges beg+sub, +4, +8, ...; lane q = lane&7 owns
// 8 fp16 channels (one uint4). 2-edge unroll -> 8 edges in flight per warp.
// Merge subgroups via shfl_xor stages 8 and 16 with flash rescaling.
template <int HEADS, bool RELU, bool TOOUT>
__global__ void __launch_bounds__(256) k_edge(const float* __restrict__ bias,
                                              float* __restrict__ outp) {
    int w = (blockIdx.x * blockDim.x + threadIdx.x) >> 5;
    int lane = threadIdx.x & 31;
    if (w >= Nn) return;
    int beg = g_rowptr[w], end = g_rowptr[w + 1];

    int sub = lane >> 3;                  // 0..3: edge phase
    int q   = lane & 7;                   // channels 8q..8q+7
    bool hi = (HEADS == 2) && (q >= 4);   // channels >= 32 -> head 1
    float2 ad2 = g_aldst[w];
    float adh = hi ? ad2.y : ad2.x;

    const uint4* fh = (const uint4*)g_feath;   // 8 uint4 per row (64 ch)
    float m = -1e30f, d = 0.f;
    float a0 = 0.f, a1 = 0.f, a2 = 0.f, a3 = 0.f;
    float a4 = 0.f, a5 = 0.f, a6 = 0.f, a7 = 0.f;

    int e = beg + sub;
    for (; e + 4 < end; e += 8) {     // two edges: e, e+4
        int s0 = g_src[e], s1 = g_src[e + 4];
        float2 as0 = g_alsrc[s0];
        float2 as1 = g_alsrc[s1];
        uint4 u0 = fh[(size_t)s0 * 8 + q];
        uint4 u1 = fh[(size_t)s1 * 8 + q];
        float l0 = lrelu((hi ? as0.y : as0.x) + adh);
        float l1 = lrelu((hi ? as1.y : as1.x) + adh);
        float nm = fmaxf(m, fmaxf(l0, l1));
        float c  = __expf(m - nm);
        float p0 = __expf(l0 - nm);
        float p1 = __expf(l1 - nm);
        float2 f0 = __half22float2(*(__half2*)&u0.x);
        float2 f1 = __half22float2(*(__half2*)&u0.y);
        float2 f2 = __half22float2(*(__half2*)&u0.z);
        float2 f3 = __half22float2(*(__half2*)&u0.w);
        float2 g0 = __half22float2(*(__half2*)&u1.x);
        float2 g1 = __half22float2(*(__half2*)&u1.y);
        float2 g2 = __half22float2(*(__half2*)&u1.z);
        float2 g3 = __half22float2(*(__half2*)&u1.w);
        a0 = a0 * c + p0 * f0.x + p1 * g0.x;
        a1 = a1 * c + p0 * f0.y + p1 * g0.y;
        a2 = a2 * c + p0 * f1.x + p1 * g1.x;
        a3 = a3 * c + p0 * f1.y + p1 * g1.y;
        a4 = a4 * c + p0 * f2.x + p1 * g2.x;
        a5 = a5 * c + p0 * f2.y + p1 * g2.y;
        a6 = a6 * c + p0 * f3.x + p1 * g3.x;
        a7 = a7 * c + p0 * f3.y + p1 * g3.y;
        d  = d  * c + p0 + p1;
        m = nm;
    }
    if (e < end) {                    // at most one remaining edge
        int s0 = g_src[e];
        float2 as0 = g_alsrc[s0];
        uint4 u0 = fh[(size_t)s0 * 8 + q];
        float l0 = lrelu((hi ? as0.y : as0.x) + adh);
        float nm = fmaxf(m, l0);
        float c  = __expf(m - nm);
        float p0 = __expf(l0 - nm);
        float2 f0 = __half22float2(*(__half2*)&u0.x);
        float2 f1 = __half22float2(*(__half2*)&u0.y);
        float2 f2 = __half22float2(*(__half2*)&u0.z);
        float2 f3 = __half22float2(*(__half2*)&u0.w);
        a0 = a0 * c + p0 * f0.x;  a1 = a1 * c + p0 * f0.y;
        a2 = a2 * c + p0 * f1.x;  a3 = a3 * c + p0 * f1.y;
        a4 = a4 * c + p0 * f2.x;  a5 = a5 * c + p0 * f2.y;
        a6 = a6 * c + p0 * f3.x;  a7 = a7 * c + p0 * f3.y;
        d  = d  * c + p0;
        m = nm;
    }

    // merge 4 subgroups: stages 8, 16
#pragma unroll
    for (int st = 8; st <= 16; st <<= 1) {
        float mo = __shfl_xor_sync(0xffffffffu, m, st);
        float M  = fmaxf(m, mo);
        float c  = __expf(m - M);
        a0 *= c; a1 *= c; a2 *= c; a3 *= c;
        a4 *= c; a5 *= c; a6 *= c; a7 *= c;
        d *= c;
        a0 += __shfl_xor_sync(0xffffffffu, a0, st);
        a1 += __shfl_xor_sync(0xffffffffu, a1, st);
        a2 += __shfl_xor_sync(0xffffffffu, a2, st);
        a3 += __shfl_xor_sync(0xffffffffu, a3, st);
        a4 += __shfl_xor_sync(0xffffffffu, a4, st);
        a5 += __shfl_xor_sync(0xffffffffu, a5, st);
        a6 += __shfl_xor_sync(0xffffffffu, a6, st);
        a7 += __shfl_xor_sync(0xffffffffu, a7, st);
        d  += __shfl_xor_sync(0xffffffffu, d, st);
        m = M;
    }
    float inv = 1.f / d;

    if (lane < 8) {
        float4 b0 = ((const float4*)bias)[q * 2];
        float4 b1 = ((const float4*)bias)[q * 2 + 1];
        float4 r0, r1;
        r0.x = a0 * inv + b0.x; r0.y = a1 * inv + b0.y;
        r0.z = a2 * inv + b0.z; r0.w = a3 * inv + b0.w;
        r1.x = a4 * inv + b1.x; r1.y = a5 * inv + b1.y;
        r1.z = a6 * inv + b1.z; r1.w = a7 * inv + b1.w;
        if (RELU) {
            r0.x = fmaxf(r0.x, 0.f); r0.y = fmaxf(r0.y, 0.f);
            r0.z = fmaxf(r0.z, 0.f); r0.w = fmaxf(r0.w, 0.f);
            r1.x = fmaxf(r1.x, 0.f); r1.y = fmaxf(r1.y, 0.f);
            r1.z = fmaxf(r1.z, 0.f); r1.w = fmaxf(r1.w, 0.f);
        }
        float* dst = TOOUT ? outp : g_buf;
        ((float4*)dst)[(size_t)w * 16 + q * 2]     = r0;
        ((float4*)dst)[(size_t)w * 16 + q * 2 + 1] = r1;
    }
}

// ---------------- launch ----------------
extern "C" void kernel_launch(void* const* d_in, const int* in_sizes, int n_in,
                              void* d_out, int out_size) {
    const float* x   = (const float*)d_in[0];
    const int*   ei  = (const int*)d_in[1];
    const float* W1  = (const float*)d_in[2];
    const float* as1 = (const float*)d_in[3];
    const float* ad1 = (const float*)d_in[4];
    const float* b1  = (const float*)d_in[5];
    const float* W2  = (const float*)d_in[6];
    const float* as2 = (const float*)d_in[7];
    const float* ad2 = (const float*)d_in[8];
    const float* b2  = (const float*)d_in[9];
    const float* W3  = (const float*)d_in[10];
    const float* as3 = (const float*)d_in[11];
    const float* ad3 = (const float*)d_in[12];
    const float* b3  = (const float*)d_in[13];
    float* out = (float*)d_out;

    cudaStream_t sa;
    cudaEvent_t e0, e1;
    cudaStreamCreateWithFlags(&sa, cudaStreamNonBlocking);
    cudaEventCreateWithFlags(&e0, cudaEventDisableTiming);
    cudaEventCreateWithFlags(&e1, cudaEventDisableTiming);

    const int GB = (Nn + 127) / 128;       // GEMM blocks (128-row tiles)
    const int WG = (Nn * 32 + 255) / 256;  // one warp per node

    // fork: CSR build runs concurrently with layer-1 GEMM.
    cudaEventRecord(e0, 0);
    cudaStreamWaitEvent(sa, e0, 0);
    k_zero<<<(Nn + 255) / 256, 256, 0, sa>>>();                 // 1
    k_hist<<<(ETOT + 255) / 256, 256, 0, sa>>>(ei);             // 2
    k_scan1<<<NB, 1024, 0, sa>>>();                             // 3
    k_gemm<128, 2, true><<<GB, 128>>>(x, W1, as1, ad1);         // 4 <- profile target
    k_scan2<<<1, 128, 0, sa>>>();                               // 5
    k_scan3<<<NB, 1024, 0, sa>>>();                             // 6
    k_scatter<<<(ETOT + 255) / 256, 256, 0, sa>>>(ei);          // 7
    cudaEventRecord(e1, sa);

    cudaStreamWaitEvent(0, e1, 0);   // join: edge kernel needs CSR
    k_edge<2, true, false><<<WG, 256>>>(b1, nullptr);

    // layer 2: 64 -> 2x32, relu
    k_gemm<64, 2, false><<<GB, 128>>>(nullptr, W2, as2, ad2);
    k_edge<2, true, false><<<WG, 256>>>(b2, nullptr);

    // layer 3: 64 -> 1x64, no relu, write d_out
    k_gemm<64, 1, false><<<GB, 128>>>(nullptr, W3, as3, ad3);
    k_edge<1, false, true><<<WG, 256>>>(b3, out);
}